// round 8
// baseline (speedup 1.0000x reference)
#include <cuda_runtime.h>
#include <cuda_bf16.h>
#include <cstdint>

#define EPS_BN 1e-5f
#define SCALE_ATTN 0.125f
#define CDIM 512
#define MROWS 8192   // B*N

// ============================ scratch (static device mem) ============================
__device__ __align__(16) __nv_bfloat16 g_xh[MROWS*CDIM], g_xl[MROWS*CDIM];
__device__ __align__(16) __nv_bfloat16 g_atth[MROWS*CDIM], g_attl[MROWS*CDIM];
__device__ __align__(16) __nv_bfloat16 g_whq[CDIM*CDIM], g_wlq[CDIM*CDIM];
__device__ __align__(16) __nv_bfloat16 g_whk[CDIM*CDIM], g_wlk[CDIM*CDIM];
__device__ __align__(16) __nv_bfloat16 g_whv[CDIM*CDIM], g_wlv[CDIM*CDIM];
__device__ __align__(16) __nv_bfloat16 g_whp[CDIM*CDIM], g_wlp[CDIM*CDIM];
__device__ float g_bq[CDIM], g_bk[CDIM], g_bv[CDIM], g_bp[CDIM];
__device__ __align__(16) float g_q[MROWS*CDIM], g_k[MROWS*CDIM], g_v[MROWS*CDIM];
__device__ __align__(16) float g_m[64*64*64];
__device__ __align__(16) float g_mpart[8*64*64*64];   // 8 partials

// ============================ portable PTX helpers ============================
__device__ __forceinline__ uint32_t smem_u32(const void* p) {
    uint32_t a;
    asm("{ .reg .u64 t; cvta.to.shared.u64 t, %1; cvt.u32.u64 %0, t; }" : "=r"(a) : "l"(p));
    return a;
}
__device__ __forceinline__ void cp16(uint32_t saddr, const void* g) {
    asm volatile("cp.async.cg.shared.global [%0], [%1], 16;" :: "r"(saddr), "l"(g) : "memory");
}
__device__ __forceinline__ void cp_commit() {
    asm volatile("cp.async.commit_group;" ::: "memory");
}
template <int N> __device__ __forceinline__ void cp_wait() {
    asm volatile("cp.async.wait_group %0;" :: "n"(N) : "memory");
}
__device__ __forceinline__ void ldsm4(uint32_t* r, uint32_t addr) {
    asm volatile("ldmatrix.sync.aligned.m8n8.x4.shared.b16 {%0,%1,%2,%3}, [%4];"
                 : "=r"(r[0]), "=r"(r[1]), "=r"(r[2]), "=r"(r[3]) : "r"(addr));
}
__device__ __forceinline__ void mma_bf16(float* c, const uint32_t* a, uint32_t b0, uint32_t b1) {
    asm volatile(
        "mma.sync.aligned.m16n8k16.row.col.f32.bf16.bf16.f32 "
        "{%0,%1,%2,%3}, {%4,%5,%6,%7}, {%8,%9}, {%0,%1,%2,%3};"
        : "+f"(c[0]), "+f"(c[1]), "+f"(c[2]), "+f"(c[3])
        : "r"(a[0]), "r"(a[1]), "r"(a[2]), "r"(a[3]), "r"(b0), "r"(b1));
}

// ============================ fused prep: BN-fold all 4 sets + split x ============================
__global__ void prep_all(
    const float* __restrict__ x,
    const float* __restrict__ w0, const float* __restrict__ b0, const float* __restrict__ g0,
    const float* __restrict__ be0, const float* __restrict__ mu0, const float* __restrict__ va0,
    const float* __restrict__ w1, const float* __restrict__ b1, const float* __restrict__ g1,
    const float* __restrict__ be1, const float* __restrict__ mu1, const float* __restrict__ va1,
    const float* __restrict__ w2, const float* __restrict__ b2, const float* __restrict__ g2,
    const float* __restrict__ be2, const float* __restrict__ mu2, const float* __restrict__ va2,
    const float* __restrict__ w3, const float* __restrict__ b3, const float* __restrict__ g3,
    const float* __restrict__ be3, const float* __restrict__ mu3, const float* __restrict__ va3)
{
    if (blockIdx.x < 4096) {
        int gi = blockIdx.x * 256 + threadIdx.x;   // 4 * 262144
        int s = gi >> 18;
        int i = gi & 262143;
        const float *w, *b, *g, *beta, *mu, *var;
        __nv_bfloat16 *wh, *wl;
        float* bias;
        if (s == 0) { w=w0;b=b0;g=g0;beta=be0;mu=mu0;var=va0; wh=g_whq;wl=g_wlq;bias=g_bq; }
        else if (s == 1) { w=w1;b=b1;g=g1;beta=be1;mu=mu1;var=va1; wh=g_whk;wl=g_wlk;bias=g_bk; }
        else if (s == 2) { w=w2;b=b2;g=g2;beta=be2;mu=mu2;var=va2; wh=g_whv;wl=g_wlv;bias=g_bv; }
        else { w=w3;b=b3;g=g3;beta=be3;mu=mu3;var=va3; wh=g_whp;wl=g_wlp;bias=g_bp; }
        int d = i >> 9;
        float sc = g[d] * rsqrtf(var[d] + EPS_BN);
        float wv = w[i] * sc;
        __nv_bfloat16 h = __float2bfloat16(wv);
        wh[i] = h;
        wl[i] = __float2bfloat16(wv - __bfloat162float(h));
        if ((i & 511) == 0) bias[d] = (b[d] - mu[d]) * sc + beta[d];
    } else {
        int i = (blockIdx.x - 4096) * 256 + threadIdx.x;   // over 1M float4
        float4 v = ((const float4*)x)[i];
        __nv_bfloat16 h0 = __float2bfloat16(v.x), h1 = __float2bfloat16(v.y);
        __nv_bfloat16 h2 = __float2bfloat16(v.z), h3 = __float2bfloat16(v.w);
        __nv_bfloat162 hh0; hh0.x = h0; hh0.y = h1;
        __nv_bfloat162 hh1; hh1.x = h2; hh1.y = h3;
        ((__nv_bfloat162*)g_xh)[i * 2 + 0] = hh0;
        ((__nv_bfloat162*)g_xh)[i * 2 + 1] = hh1;
        __nv_bfloat162 ll0, ll1;
        ll0.x = __float2bfloat16(v.x - __bfloat162float(h0));
        ll0.y = __float2bfloat16(v.y - __bfloat162float(h1));
        ll1.x = __float2bfloat16(v.z - __bfloat162float(h2));
        ll1.y = __float2bfloat16(v.w - __bfloat162float(h3));
        ((__nv_bfloat162*)g_xl)[i * 2 + 0] = ll0;
        ((__nv_bfloat162*)g_xl)[i * 2 + 1] = ll1;
    }
}

// ============================ HMMA GEMM v5: C = relu(A @ W^T + bias) ============================
// 128x128 CTA tile, BK=32, 128 threads (4 warps, 64x64 warp tiles -> 0.167 LDSM/MMA),
// 2-stage cp.async, 2 CTAs/SM.
#define BK 32
#define NSTAGE (CDIM / BK)          // 16
#define RPITCH 80
#define T_TB (128 * RPITCH)         // 10240 per operand tile
#define STAGEB (4 * T_TB)           // 40960: [Ah, Al, Wh, Wl]
#define GEMM_SMEM (2 * STAGEB)      // 81920

__global__ __launch_bounds__(128, 2)
void gemm_tc(float* __restrict__ Cext, int mode)
{
    extern __shared__ char smem[];
    const __nv_bfloat16 *Ah, *Al, *Wh, *Wl;
    const float* bias;
    float* C;
    int bn;
    if (mode == 0) {
        int sel = blockIdx.x >> 2;          // 0=q, 1=k, 2=v
        bn = (blockIdx.x & 3) * 128;
        Ah = g_xh; Al = g_xl;
        Wh = (sel == 0) ? g_whq : (sel == 1) ? g_whk : g_whv;
        Wl = (sel == 0) ? g_wlq : (sel == 1) ? g_wlk : g_wlv;
        bias = (sel == 0) ? g_bq : (sel == 1) ? g_bk : g_bv;
        C = (sel == 0) ? g_q : (sel == 1) ? g_k : g_v;
    } else {
        bn = blockIdx.x * 128;
        Ah = g_atth; Al = g_attl;
        Wh = g_whp; Wl = g_wlp; bias = g_bp;
        C = Cext;
    }
    const int bm = blockIdx.y * 128;

    const uint32_t sb = smem_u32(smem);
    const int tid = threadIdx.x;
    const int wid = tid >> 5, lane = tid & 31;
    const int wm = wid & 1, wn = wid >> 1;   // 2(m) x 2(n), 64x64 per warp

    const __nv_bfloat16* srcA[2] = { Ah + (size_t)bm * CDIM, Al + (size_t)bm * CDIM };
    const __nv_bfloat16* srcW[2] = { Wh + (size_t)bn * CDIM, Wl + (size_t)bn * CDIM };

    // 2048 16B-chunks per stage, 16 per thread
    auto load_stage = [&](int s, int buf) {
        uint32_t sbase = sb + buf * STAGEB;
        int kof = s * BK;
#pragma unroll
        for (int t = 0; t < 16; ++t) {
            int idx = tid + t * 128;
            int ten = idx >> 9;              // 0=Ah 1=Al 2=Wh 3=Wl
            int v = idx & 511;
            int row = v >> 2, ch = v & 3;
            const __nv_bfloat16* g =
                (ten < 2 ? srcA[ten] : srcW[ten - 2]) + (size_t)row * CDIM + kof + ch * 8;
            cp16(sbase + ten * T_TB + row * RPITCH + ch * 16, g);
        }
        cp_commit();
    };

    float acc[4][8][4];
#pragma unroll
    for (int i = 0; i < 4; ++i)
#pragma unroll
        for (int j = 0; j < 8; ++j)
#pragma unroll
            for (int k = 0; k < 4; ++k) acc[i][j][k] = 0.f;

    const int g8 = lane >> 3, l8 = lane & 7;
    const int a_row = (g8 & 1) * 8 + l8;
    const int a_k = (g8 >> 1) * 8;
    const int w_row = (g8 >> 1) * 8 + l8;
    const int w_k = (g8 & 1) * 8;

    const uint32_t aoffL = (wm * 64 + a_row) * RPITCH + a_k * 2;
    const uint32_t woffL = (wn * 64 + w_row) * RPITCH + w_k * 2;

    load_stage(0, 0);

    for (int s = 0; s < NSTAGE; ++s) {
        cp_wait<0>();
        __syncthreads();
        if (s + 1 < NSTAGE) load_stage(s + 1, (s + 1) & 1);

        const uint32_t base = sb + (s & 1) * STAGEB;
        const uint32_t aB = base + aoffL;
        const uint32_t wB = base + 2 * T_TB + woffL;

#pragma unroll
        for (int kk = 0; kk < BK; kk += 16) {
            // W frags: 4 n16-groups x (hi,lo) = 8 LDSM.x4
            uint32_t whf[4][4], wlf[4][4];
#pragma unroll
            for (int j = 0; j < 4; ++j) {
                uint32_t off = wB + j * (16 * RPITCH) + kk * 2;
                ldsm4(whf[j], off);
                ldsm4(wlf[j], off + T_TB);
            }
            // A frags: double-buffered over mi: 8 LDSM.x4 total
            uint32_t ahf[2][4], alf[2][4];
            ldsm4(ahf[0], aB + kk * 2);
            ldsm4(alf[0], aB + kk * 2 + T_TB);
#pragma unroll
            for (int mi = 0; mi < 4; ++mi) {
                const int cur = mi & 1;
                if (mi < 3) {
                    uint32_t off = aB + (mi + 1) * (16 * RPITCH) + kk * 2;
                    ldsm4(ahf[cur ^ 1], off);
                    ldsm4(alf[cur ^ 1], off + T_TB);
                }
                // 24 MMAs; each accumulator reused 8 issues apart
#pragma unroll
                for (int nj = 0; nj < 8; ++nj)
                    mma_bf16(acc[mi][nj], ahf[cur], whf[nj >> 1][(nj & 1) * 2], whf[nj >> 1][(nj & 1) * 2 + 1]);
#pragma unroll
                for (int nj = 0; nj < 8; ++nj)
                    mma_bf16(acc[mi][nj], ahf[cur], wlf[nj >> 1][(nj & 1) * 2], wlf[nj >> 1][(nj & 1) * 2 + 1]);
#pragma unroll
                for (int nj = 0; nj < 8; ++nj)
                    mma_bf16(acc[mi][nj], alf[cur], whf[nj >> 1][(nj & 1) * 2], whf[nj >> 1][(nj & 1) * 2 + 1]);
            }
        }
    }

    const int r_in = lane >> 2;
    const int c_in = (lane & 3) * 2;
#pragma unroll
    for (int mi = 0; mi < 4; ++mi) {
        int r0 = bm + wm * 64 + mi * 16 + r_in;
#pragma unroll
        for (int nj = 0; nj < 8; ++nj) {
            int c0 = bn + wn * 64 + nj * 8 + c_in;
            float b0 = bias[c0], b1 = bias[c0 + 1];
            float2 lo, hi;
            lo.x = fmaxf(acc[mi][nj][0] + b0, 0.f);
            lo.y = fmaxf(acc[mi][nj][1] + b1, 0.f);
            hi.x = fmaxf(acc[mi][nj][2] + b0, 0.f);
            hi.y = fmaxf(acc[mi][nj][3] + b1, 0.f);
            *(float2*)(C + (size_t)r0 * CDIM + c0) = lo;
            *(float2*)(C + (size_t)(r0 + 8) * CDIM + c0) = hi;
        }
    }
}

// ============================ attention middle ============================
__global__ __launch_bounds__(128)
void kv_outer_partial()
{
    int bh = blockIdx.x, part = blockIdx.y;
    int b = bh >> 3, h = bh & 7;
    __shared__ float Ks[32][64];
    __shared__ float Vs[32][64];
    int tid = threadIdx.x;
    int tx = tid & 15;                // e-group: 4 per thread
    int ty = tid >> 4;                // d-group: 8 per thread
    const float* kbase = g_k + ((size_t)b * 1024) * CDIM + h * 64;
    const float* vbase = g_v + ((size_t)b * 1024) * CDIM + h * 64;

    float acc[8][4];
#pragma unroll
    for (int i = 0; i < 8; ++i)
#pragma unroll
        for (int j = 0; j < 4; ++j) acc[i][j] = 0.f;

    int nbeg = part * 128;
    for (int n0 = nbeg; n0 < nbeg + 128; n0 += 32) {
#pragma unroll
        for (int u = 0; u < 4; ++u) {
            int v = tid + u * 128;
            int r = v >> 4, c4 = v & 15;
            *(float4*)&Ks[r][c4 * 4] = *(const float4*)(kbase + (size_t)(n0 + r) * CDIM + c4 * 4);
            *(float4*)&Vs[r][c4 * 4] = *(const float4*)(vbase + (size_t)(n0 + r) * CDIM + c4 * 4);
        }
        __syncthreads();
#pragma unroll
        for (int nn = 0; nn < 32; ++nn) {
            float4 k0 = *(const float4*)&Ks[nn][ty * 8];
            float4 k1 = *(const float4*)&Ks[nn][ty * 8 + 4];
            float4 vv = *(const float4*)&Vs[nn][tx * 4];
            float ka[8] = {k0.x, k0.y, k0.z, k0.w, k1.x, k1.y, k1.z, k1.w};
            float va[4] = {vv.x, vv.y, vv.z, vv.w};
#pragma unroll
            for (int i = 0; i < 8; ++i)
#pragma unroll
                for (int j = 0; j < 4; ++j)
                    acc[i][j] = fmaf(ka[i], va[j], acc[i][j]);
        }
        __syncthreads();
    }

    float* mp = g_mpart + ((size_t)part * 64 + bh) * 4096;
#pragma unroll
    for (int i = 0; i < 8; ++i) {
        float* row = mp + (ty * 8 + i) * 64 + tx * 4;
        float4 o = {acc[i][0], acc[i][1], acc[i][2], acc[i][3]};
        *(float4*)row = o;
    }
}

__global__ void kv_reduce8()
{
    int i = blockIdx.x * blockDim.x + threadIdx.x;   // over 65536 float4
    float4 s = ((const float4*)g_mpart)[i];
#pragma unroll
    for (int p = 1; p < 8; ++p) {
        float4 t = ((const float4*)g_mpart)[p * 65536 + i];
        s.x += t.x; s.y += t.y; s.z += t.z; s.w += t.w;
    }
    s.x *= SCALE_ATTN; s.y *= SCALE_ATTN; s.z *= SCALE_ATTN; s.w *= SCALE_ATTN;
    ((float4*)g_m)[i] = s;
}

__global__ __launch_bounds__(256)
void qm_relu_split()
{
    int nt = blockIdx.x, h = blockIdx.y, b = blockIdx.z;
    __shared__ float Qs[64][65];
    __shared__ float Ms[64][68];
    int tid = threadIdx.x;
    const float* qbase = g_q + ((size_t)(b * 1024 + nt * 64)) * CDIM + h * 64;
    const float* mbase = g_m + (size_t)(b * 8 + h) * 4096;
#pragma unroll
    for (int u = 0; u < 4; ++u) {
        int v = tid + u * 256;
        int r = v >> 4, c4 = v & 15;
        float4 t = *(const float4*)(qbase + (size_t)r * CDIM + c4 * 4);
        Qs[r][c4 * 4 + 0] = t.x; Qs[r][c4 * 4 + 1] = t.y;
        Qs[r][c4 * 4 + 2] = t.z; Qs[r][c4 * 4 + 3] = t.w;
        *(float4*)&Ms[r][c4 * 4] = *(const float4*)(mbase + r * 64 + c4 * 4);
    }
    __syncthreads();
    int r = tid >> 2, quarter = tid & 3;
    float acc[16];
#pragma unroll
    for (int e = 0; e < 16; ++e) acc[e] = 0.f;
#pragma unroll
    for (int d = 0; d < 64; ++d) {
        float qv = Qs[r][d];
#pragma unroll
        for (int e4 = 0; e4 < 4; ++e4) {
            float4 m = *(const float4*)&Ms[d][quarter * 16 + e4 * 4];
            acc[e4 * 4 + 0] = fmaf(qv, m.x, acc[e4 * 4 + 0]);
            acc[e4 * 4 + 1] = fmaf(qv, m.y, acc[e4 * 4 + 1]);
            acc[e4 * 4 + 2] = fmaf(qv, m.z, acc[e4 * 4 + 2]);
            acc[e4 * 4 + 3] = fmaf(qv, m.w, acc[e4 * 4 + 3]);
        }
    }
    size_t obase = ((size_t)(b * 1024 + nt * 64 + r)) * CDIM + h * 64 + quarter * 16;
#pragma unroll
    for (int e2 = 0; e2 < 8; ++e2) {
        float v0 = fmaxf(acc[e2 * 2 + 0], 0.f);
        float v1 = fmaxf(acc[e2 * 2 + 1], 0.f);
        __nv_bfloat16 h0 = __float2bfloat16(v0);
        __nv_bfloat16 h1 = __float2bfloat16(v1);
        __nv_bfloat162 hh; hh.x = h0; hh.y = h1;
        __nv_bfloat162 ll;
        ll.x = __float2bfloat16(v0 - __bfloat162float(h0));
        ll.y = __float2bfloat16(v1 - __bfloat162float(h1));
        *(__nv_bfloat162*)(g_atth + obase + e2 * 2) = hh;
        *(__nv_bfloat162*)(g_attl + obase + e2 * 2) = ll;
    }
}

// ============================ host launch ============================
extern "C" void kernel_launch(void* const* d_in, const int* in_sizes, int n_in,
                              void* d_out, int out_size)
{
    (void)in_sizes; (void)n_in; (void)out_size;
    const float* x = (const float*)d_in[0];
    const float** p = (const float**)(d_in + 1);   // 24 params: 4 sets x 6

    cudaFuncSetAttribute(gemm_tc, cudaFuncAttributeMaxDynamicSharedMemorySize, GEMM_SMEM);

    prep_all<<<8192, 256>>>(x,
        p[0], p[1], p[2], p[3], p[4], p[5],
        p[6], p[7], p[8], p[9], p[10], p[11],
        p[12], p[13], p[14], p[15], p[16], p[17],
        p[18], p[19], p[20], p[21], p[22], p[23]);

    // fused QKV: grid (12, 64) = 768 CTAs, 128 thr, 2 CTAs/SM
    gemm_tc<<<dim3(12, 64), 128, GEMM_SMEM>>>(nullptr, 0);

    kv_outer_partial<<<dim3(64, 8), 128>>>();
    kv_reduce8<<<512, 128>>>();
    qm_relu_split<<<dim3(16, 8, 8), 256>>>();

    // P projection
    gemm_tc<<<dim3(4, 64), 128, GEMM_SMEM>>>((float*)d_out, 1);
}

// round 9
// speedup vs baseline: 1.2139x; 1.2139x over previous
#include <cuda_runtime.h>
#include <cuda_fp16.h>
#include <cstdint>

#define EPS_BN 1e-5f
#define SCALE_ATTN 0.125f
#define CDIM 512
#define MROWS 8192   // B*N
#define WSCALE 64.0f
#define INV_WSCALE (1.0f / 64.0f)

// ============================ scratch (static device mem) ============================
__device__ __align__(16) __half g_xf[MROWS*CDIM];
__device__ __align__(16) __half g_attf[MROWS*CDIM];
__device__ __align__(16) __half g_whq[CDIM*CDIM], g_wlq[CDIM*CDIM];
__device__ __align__(16) __half g_whk[CDIM*CDIM], g_wlk[CDIM*CDIM];
__device__ __align__(16) __half g_whv[CDIM*CDIM], g_wlv[CDIM*CDIM];
__device__ __align__(16) __half g_whp[CDIM*CDIM], g_wlp[CDIM*CDIM];
__device__ float g_bq[CDIM], g_bk[CDIM], g_bv[CDIM], g_bp[CDIM];
__device__ __align__(16) float g_q[MROWS*CDIM], g_k[MROWS*CDIM], g_v[MROWS*CDIM];
__device__ __align__(16) float g_m[64*64*64];
__device__ __align__(16) float g_mpart[8*64*64*64];   // 8 partials

// ============================ portable PTX helpers ============================
__device__ __forceinline__ uint32_t smem_u32(const void* p) {
    uint32_t a;
    asm("{ .reg .u64 t; cvta.to.shared.u64 t, %1; cvt.u32.u64 %0, t; }" : "=r"(a) : "l"(p));
    return a;
}
__device__ __forceinline__ void cp16(uint32_t saddr, const void* g) {
    asm volatile("cp.async.cg.shared.global [%0], [%1], 16;" :: "r"(saddr), "l"(g) : "memory");
}
__device__ __forceinline__ void cp_commit() {
    asm volatile("cp.async.commit_group;" ::: "memory");
}
template <int N> __device__ __forceinline__ void cp_wait() {
    asm volatile("cp.async.wait_group %0;" :: "n"(N) : "memory");
}
__device__ __forceinline__ void ldsm4(uint32_t* r, uint32_t addr) {
    asm volatile("ldmatrix.sync.aligned.m8n8.x4.shared.b16 {%0,%1,%2,%3}, [%4];"
                 : "=r"(r[0]), "=r"(r[1]), "=r"(r[2]), "=r"(r[3]) : "r"(addr));
}
__device__ __forceinline__ void mma_f16(float* c, const uint32_t* a, uint32_t b0, uint32_t b1) {
    asm volatile(
        "mma.sync.aligned.m16n8k16.row.col.f32.f16.f16.f32 "
        "{%0,%1,%2,%3}, {%4,%5,%6,%7}, {%8,%9}, {%0,%1,%2,%3};"
        : "+f"(c[0]), "+f"(c[1]), "+f"(c[2]), "+f"(c[3])
        : "r"(a[0]), "r"(a[1]), "r"(a[2]), "r"(a[3]), "r"(b0), "r"(b1));
}

// ============================ fused prep: BN-fold all 4 sets + x->fp16 ============================
// blocks [0,4096): fold 4x262144 weight elems (scaled x64, split fp16 hi/lo exactly).
// blocks [4096,8192): x -> single fp16.
__global__ void prep_all(
    const float* __restrict__ x,
    const float* __restrict__ w0, const float* __restrict__ b0, const float* __restrict__ g0,
    const float* __restrict__ be0, const float* __restrict__ mu0, const float* __restrict__ va0,
    const float* __restrict__ w1, const float* __restrict__ b1, const float* __restrict__ g1,
    const float* __restrict__ be1, const float* __restrict__ mu1, const float* __restrict__ va1,
    const float* __restrict__ w2, const float* __restrict__ b2, const float* __restrict__ g2,
    const float* __restrict__ be2, const float* __restrict__ mu2, const float* __restrict__ va2,
    const float* __restrict__ w3, const float* __restrict__ b3, const float* __restrict__ g3,
    const float* __restrict__ be3, const float* __restrict__ mu3, const float* __restrict__ va3)
{
    if (blockIdx.x < 4096) {
        int gi = blockIdx.x * 256 + threadIdx.x;   // 4 * 262144
        int s = gi >> 18;
        int i = gi & 262143;
        const float *w, *b, *g, *beta, *mu, *var;
        __half *wh, *wl;
        float* bias;
        if (s == 0) { w=w0;b=b0;g=g0;beta=be0;mu=mu0;var=va0; wh=g_whq;wl=g_wlq;bias=g_bq; }
        else if (s == 1) { w=w1;b=b1;g=g1;beta=be1;mu=mu1;var=va1; wh=g_whk;wl=g_wlk;bias=g_bk; }
        else if (s == 2) { w=w2;b=b2;g=g2;beta=be2;mu=mu2;var=va2; wh=g_whv;wl=g_wlv;bias=g_bv; }
        else { w=w3;b=b3;g=g3;beta=be3;mu=mu3;var=va3; wh=g_whp;wl=g_wlp;bias=g_bp; }
        int d = i >> 9;
        float sc = g[d] * rsqrtf(var[d] + EPS_BN);
        float wv = w[i] * sc * WSCALE;                 // scaled x64 -> lo term stays normal fp16
        __half h = __float2half_rn(wv);
        wh[i] = h;
        wl[i] = __float2half_rn(wv - __half2float(h)); // exact residual split
        if ((i & 511) == 0) bias[d] = (b[d] - mu[d]) * sc + beta[d];
    } else {
        int i = (blockIdx.x - 4096) * 256 + threadIdx.x;   // over 1M float4
        float4 v = ((const float4*)x)[i];
        __half2 a; a.x = __float2half_rn(v.x); a.y = __float2half_rn(v.y);
        __half2 b; b.x = __float2half_rn(v.z); b.y = __float2half_rn(v.w);
        ((__half2*)g_xf)[i * 2 + 0] = a;
        ((__half2*)g_xf)[i * 2 + 1] = b;
    }
}

// ============================ HMMA GEMM v6 (fp16, 2-product): C = relu((A@W^T)/64 + bias) ======
// 128x128 CTA tile, BK=32, 256 threads (8 warps 2m x 4n, 64x32 warp tiles), 2-stage cp.async,
// 3 operand tiles per stage [Af, Wh, Wl], 2 CTAs/SM.
#define BK 32
#define NSTAGE (CDIM / BK)          // 16
#define RPITCH 80                   // 64B data + 16B pad
#define T_TB (128 * RPITCH)         // 10240 per operand tile
#define STAGEB (3 * T_TB)           // 30720: [Af, Wh, Wl]
#define GEMM_SMEM (2 * STAGEB)      // 61440

__global__ __launch_bounds__(256, 2)
void gemm_tc(float* __restrict__ Cext, int mode)
{
    extern __shared__ char smem[];
    const __half *Af, *Wh, *Wl;
    const float* bias;
    float* C;
    int bn;
    if (mode == 0) {
        int sel = blockIdx.x >> 2;          // 0=q, 1=k, 2=v
        bn = (blockIdx.x & 3) * 128;
        Af = g_xf;
        Wh = (sel == 0) ? g_whq : (sel == 1) ? g_whk : g_whv;
        Wl = (sel == 0) ? g_wlq : (sel == 1) ? g_wlk : g_wlv;
        bias = (sel == 0) ? g_bq : (sel == 1) ? g_bk : g_bv;
        C = (sel == 0) ? g_q : (sel == 1) ? g_k : g_v;
    } else {
        bn = blockIdx.x * 128;
        Af = g_attf;
        Wh = g_whp; Wl = g_wlp; bias = g_bp;
        C = Cext;
    }
    const int bm = blockIdx.y * 128;

    const uint32_t sb = smem_u32(smem);
    const int tid = threadIdx.x;
    const int wid = tid >> 5, lane = tid & 31;
    const int wm = wid & 1, wn = wid >> 1;   // 2(m) x 4(n), 64x32 per warp

    const __half* srcA = Af + (size_t)bm * CDIM;
    const __half* srcW[2] = { Wh + (size_t)bn * CDIM, Wl + (size_t)bn * CDIM };

    // 1536 16B-chunks per stage (3 tensors x 512), 6 per thread
    auto load_stage = [&](int s, int buf) {
        uint32_t sbase = sb + buf * STAGEB;
        int kof = s * BK;
#pragma unroll
        for (int t = 0; t < 6; ++t) {
            int idx = tid + t * 256;
            int ten = idx >> 9;              // 0=Af 1=Wh 2=Wl
            int v = idx & 511;
            int row = v >> 2, ch = v & 3;
            const __half* g =
                (ten == 0 ? srcA : srcW[ten - 1]) + (size_t)row * CDIM + kof + ch * 8;
            cp16(sbase + ten * T_TB + row * RPITCH + ch * 16, g);
        }
        cp_commit();
    };

    float acc[4][4][4];
#pragma unroll
    for (int i = 0; i < 4; ++i)
#pragma unroll
        for (int j = 0; j < 4; ++j)
#pragma unroll
            for (int k = 0; k < 4; ++k) acc[i][j][k] = 0.f;

    const int g8 = lane >> 3, l8 = lane & 7;
    const int a_row = (g8 & 1) * 8 + l8;
    const int a_k = (g8 >> 1) * 8;
    const int w_row = (g8 >> 1) * 8 + l8;
    const int w_k = (g8 & 1) * 8;

    const uint32_t aoffL = (wm * 64 + a_row) * RPITCH + a_k * 2;
    const uint32_t woffL = (wn * 32 + w_row) * RPITCH + w_k * 2;

    load_stage(0, 0);

    for (int s = 0; s < NSTAGE; ++s) {
        cp_wait<0>();
        __syncthreads();
        if (s + 1 < NSTAGE) load_stage(s + 1, (s + 1) & 1);

        const uint32_t base = sb + (s & 1) * STAGEB;
        const uint32_t aB = base + aoffL;
        const uint32_t wB = base + T_TB + woffL;

#pragma unroll
        for (int kk = 0; kk < BK; kk += 16) {
            uint32_t whf[2][4], wlf[2][4];
#pragma unroll
            for (int j = 0; j < 2; ++j) {
                uint32_t off = wB + j * (16 * RPITCH) + kk * 2;
                ldsm4(whf[j], off);
                ldsm4(wlf[j], off + T_TB);
            }
            uint32_t ahf[2][4];
            ldsm4(ahf[0], aB + kk * 2);
#pragma unroll
            for (int mi = 0; mi < 4; ++mi) {
                const int cur = mi & 1;
                if (mi < 3) ldsm4(ahf[cur ^ 1], aB + (mi + 1) * (16 * RPITCH) + kk * 2);
                // 2 products; each accumulator reused 4 issues apart
#pragma unroll
                for (int nj = 0; nj < 4; ++nj)
                    mma_f16(acc[mi][nj], ahf[cur], whf[nj >> 1][(nj & 1) * 2], whf[nj >> 1][(nj & 1) * 2 + 1]);
#pragma unroll
                for (int nj = 0; nj < 4; ++nj)
                    mma_f16(acc[mi][nj], ahf[cur], wlf[nj >> 1][(nj & 1) * 2], wlf[nj >> 1][(nj & 1) * 2 + 1]);
            }
        }
    }

    const int r_in = lane >> 2;
    const int c_in = (lane & 3) * 2;
#pragma unroll
    for (int mi = 0; mi < 4; ++mi) {
        int r0 = bm + wm * 64 + mi * 16 + r_in;
#pragma unroll
        for (int nj = 0; nj < 4; ++nj) {
            int c0 = bn + wn * 32 + nj * 8 + c_in;
            float b0 = bias[c0], b1 = bias[c0 + 1];
            float2 lo, hi;
            lo.x = fmaxf(fmaf(acc[mi][nj][0], INV_WSCALE, b0), 0.f);
            lo.y = fmaxf(fmaf(acc[mi][nj][1], INV_WSCALE, b1), 0.f);
            hi.x = fmaxf(fmaf(acc[mi][nj][2], INV_WSCALE, b0), 0.f);
            hi.y = fmaxf(fmaf(acc[mi][nj][3], INV_WSCALE, b1), 0.f);
            *(float2*)(C + (size_t)r0 * CDIM + c0) = lo;
            *(float2*)(C + (size_t)(r0 + 8) * CDIM + c0) = hi;
        }
    }
}

// ============================ attention middle ============================
__global__ __launch_bounds__(128)
void kv_outer_partial()
{
    int bh = blockIdx.x, part = blockIdx.y;
    int b = bh >> 3, h = bh & 7;
    __shared__ float Ks[32][64];
    __shared__ float Vs[32][64];
    int tid = threadIdx.x;
    int tx = tid & 15;                // e-group: 4 per thread
    int ty = tid >> 4;                // d-group: 8 per thread
    const float* kbase = g_k + ((size_t)b * 1024) * CDIM + h * 64;
    const float* vbase = g_v + ((size_t)b * 1024) * CDIM + h * 64;

    float acc[8][4];
#pragma unroll
    for (int i = 0; i < 8; ++i)
#pragma unroll
        for (int j = 0; j < 4; ++j) acc[i][j] = 0.f;

    int nbeg = part * 128;
    for (int n0 = nbeg; n0 < nbeg + 128; n0 += 32) {
#pragma unroll
        for (int u = 0; u < 4; ++u) {
            int v = tid + u * 128;
            int r = v >> 4, c4 = v & 15;
            *(float4*)&Ks[r][c4 * 4] = *(const float4*)(kbase + (size_t)(n0 + r) * CDIM + c4 * 4);
            *(float4*)&Vs[r][c4 * 4] = *(const float4*)(vbase + (size_t)(n0 + r) * CDIM + c4 * 4);
        }
        __syncthreads();
#pragma unroll
        for (int nn = 0; nn < 32; ++nn) {
            float4 k0 = *(const float4*)&Ks[nn][ty * 8];
            float4 k1 = *(const float4*)&Ks[nn][ty * 8 + 4];
            float4 vv = *(const float4*)&Vs[nn][tx * 4];
            float ka[8] = {k0.x, k0.y, k0.z, k0.w, k1.x, k1.y, k1.z, k1.w};
            float va[4] = {vv.x, vv.y, vv.z, vv.w};
#pragma unroll
            for (int i = 0; i < 8; ++i)
#pragma unroll
                for (int j = 0; j < 4; ++j)
                    acc[i][j] = fmaf(ka[i], va[j], acc[i][j]);
        }
        __syncthreads();
    }

    float* mp = g_mpart + ((size_t)part * 64 + bh) * 4096;
#pragma unroll
    for (int i = 0; i < 8; ++i) {
        float* row = mp + (ty * 8 + i) * 64 + tx * 4;
        float4 o = {acc[i][0], acc[i][1], acc[i][2], acc[i][3]};
        *(float4*)row = o;
    }
}

__global__ void kv_reduce8()
{
    int i = blockIdx.x * blockDim.x + threadIdx.x;   // over 65536 float4
    float4 s = ((const float4*)g_mpart)[i];
#pragma unroll
    for (int p = 1; p < 8; ++p) {
        float4 t = ((const float4*)g_mpart)[p * 65536 + i];
        s.x += t.x; s.y += t.y; s.z += t.z; s.w += t.w;
    }
    s.x *= SCALE_ATTN; s.y *= SCALE_ATTN; s.z *= SCALE_ATTN; s.w *= SCALE_ATTN;
    ((float4*)g_m)[i] = s;
}

// att = relu(q @ M) -> single fp16
__global__ __launch_bounds__(256)
void qm_relu_split()
{
    int nt = blockIdx.x, h = blockIdx.y, b = blockIdx.z;
    __shared__ float Qs[64][65];
    __shared__ float Ms[64][68];
    int tid = threadIdx.x;
    const float* qbase = g_q + ((size_t)(b * 1024 + nt * 64)) * CDIM + h * 64;
    const float* mbase = g_m + (size_t)(b * 8 + h) * 4096;
#pragma unroll
    for (int u = 0; u < 4; ++u) {
        int v = tid + u * 256;
        int r = v >> 4, c4 = v & 15;
        float4 t = *(const float4*)(qbase + (size_t)r * CDIM + c4 * 4);
        Qs[r][c4 * 4 + 0] = t.x; Qs[r][c4 * 4 + 1] = t.y;
        Qs[r][c4 * 4 + 2] = t.z; Qs[r][c4 * 4 + 3] = t.w;
        *(float4*)&Ms[r][c4 * 4] = *(const float4*)(mbase + r * 64 + c4 * 4);
    }
    __syncthreads();
    int r = tid >> 2, quarter = tid & 3;
    float acc[16];
#pragma unroll
    for (int e = 0; e < 16; ++e) acc[e] = 0.f;
#pragma unroll
    for (int d = 0; d < 64; ++d) {
        float qv = Qs[r][d];
#pragma unroll
        for (int e4 = 0; e4 < 4; ++e4) {
            float4 m = *(const float4*)&Ms[d][quarter * 16 + e4 * 4];
            acc[e4 * 4 + 0] = fmaf(qv, m.x, acc[e4 * 4 + 0]);
            acc[e4 * 4 + 1] = fmaf(qv, m.y, acc[e4 * 4 + 1]);
            acc[e4 * 4 + 2] = fmaf(qv, m.z, acc[e4 * 4 + 2]);
            acc[e4 * 4 + 3] = fmaf(qv, m.w, acc[e4 * 4 + 3]);
        }
    }
    size_t obase = ((size_t)(b * 1024 + nt * 64 + r)) * CDIM + h * 64 + quarter * 16;
#pragma unroll
    for (int e2 = 0; e2 < 8; ++e2) {
        __half2 hh;
        hh.x = __float2half_rn(fmaxf(acc[e2 * 2 + 0], 0.f));
        hh.y = __float2half_rn(fmaxf(acc[e2 * 2 + 1], 0.f));
        *(__half2*)(g_attf + obase + e2 * 2) = hh;
    }
}

// ============================ host launch ============================
extern "C" void kernel_launch(void* const* d_in, const int* in_sizes, int n_in,
                              void* d_out, int out_size)
{
    (void)in_sizes; (void)n_in; (void)out_size;
    const float* x = (const float*)d_in[0];
    const float** p = (const float**)(d_in + 1);   // 24 params: 4 sets x 6

    cudaFuncSetAttribute(gemm_tc, cudaFuncAttributeMaxDynamicSharedMemorySize, GEMM_SMEM);

    prep_all<<<8192, 256>>>(x,
        p[0], p[1], p[2], p[3], p[4], p[5],
        p[6], p[7], p[8], p[9], p[10], p[11],
        p[12], p[13], p[14], p[15], p[16], p[17],
        p[18], p[19], p[20], p[21], p[22], p[23]);

    // fused QKV: grid (12, 64) = 768 CTAs, 256 thr, 2 CTAs/SM
    gemm_tc<<<dim3(12, 64), 256, GEMM_SMEM>>>(nullptr, 0);

    kv_outer_partial<<<dim3(64, 8), 128>>>();
    kv_reduce8<<<512, 128>>>();
    qm_relu_split<<<dim3(16, 8, 8), 256>>>();

    // P projection
    gemm_tc<<<dim3(4, 64), 256, GEMM_SMEM>>>((float*)d_out, 1);
}

// round 10
// speedup vs baseline: 1.5490x; 1.2761x over previous
#include <cuda_runtime.h>
#include <cuda_fp16.h>
#include <cstdint>

#define EPS_BN 1e-5f
#define SCALE_ATTN 0.125f
#define CDIM 512
#define MROWS 8192   // B*N

// ============================ scratch (static device mem) ============================
__device__ __align__(16) __half g_xf[MROWS*CDIM];
__device__ __align__(16) __half g_attf[MROWS*CDIM];
__device__ __align__(16) __half g_wq[CDIM*CDIM], g_wk[CDIM*CDIM];
__device__ __align__(16) __half g_wv[CDIM*CDIM], g_wp[CDIM*CDIM];
__device__ float g_bq[CDIM], g_bk[CDIM], g_bv[CDIM], g_bp[CDIM];
__device__ __align__(16) float g_q[MROWS*CDIM], g_k[MROWS*CDIM], g_v[MROWS*CDIM];
__device__ __align__(16) float g_m[64*64*64];
__device__ __align__(16) float g_mpart[8*64*64*64];   // 8 partials

// ============================ portable PTX helpers ============================
__device__ __forceinline__ uint32_t smem_u32(const void* p) {
    uint32_t a;
    asm("{ .reg .u64 t; cvta.to.shared.u64 t, %1; cvt.u32.u64 %0, t; }" : "=r"(a) : "l"(p));
    return a;
}
__device__ __forceinline__ void cp16(uint32_t saddr, const void* g) {
    asm volatile("cp.async.cg.shared.global [%0], [%1], 16;" :: "r"(saddr), "l"(g) : "memory");
}
__device__ __forceinline__ void cp_commit() {
    asm volatile("cp.async.commit_group;" ::: "memory");
}
template <int N> __device__ __forceinline__ void cp_wait() {
    asm volatile("cp.async.wait_group %0;" :: "n"(N) : "memory");
}
__device__ __forceinline__ void ldsm4(uint32_t* r, uint32_t addr) {
    asm volatile("ldmatrix.sync.aligned.m8n8.x4.shared.b16 {%0,%1,%2,%3}, [%4];"
                 : "=r"(r[0]), "=r"(r[1]), "=r"(r[2]), "=r"(r[3]) : "r"(addr));
}
__device__ __forceinline__ void mma_f16(float* c, const uint32_t* a, uint32_t b0, uint32_t b1) {
    asm volatile(
        "mma.sync.aligned.m16n8k16.row.col.f32.f16.f16.f32 "
        "{%0,%1,%2,%3}, {%4,%5,%6,%7}, {%8,%9}, {%0,%1,%2,%3};"
        : "+f"(c[0]), "+f"(c[1]), "+f"(c[2]), "+f"(c[3])
        : "r"(a[0]), "r"(a[1]), "r"(a[2]), "r"(a[3]), "r"(b0), "r"(b1));
}

// ============================ fused prep: BN-fold all 4 sets + x->fp16 ============================
// blocks [0,4096): fold 4x262144 weight elems -> single fp16.
// blocks [4096,8192): x -> single fp16.
__global__ void prep_all(
    const float* __restrict__ x,
    const float* __restrict__ w0, const float* __restrict__ b0, const float* __restrict__ g0,
    const float* __restrict__ be0, const float* __restrict__ mu0, const float* __restrict__ va0,
    const float* __restrict__ w1, const float* __restrict__ b1, const float* __restrict__ g1,
    const float* __restrict__ be1, const float* __restrict__ mu1, const float* __restrict__ va1,
    const float* __restrict__ w2, const float* __restrict__ b2, const float* __restrict__ g2,
    const float* __restrict__ be2, const float* __restrict__ mu2, const float* __restrict__ va2,
    const float* __restrict__ w3, const float* __restrict__ b3, const float* __restrict__ g3,
    const float* __restrict__ be3, const float* __restrict__ mu3, const float* __restrict__ va3)
{
    if (blockIdx.x < 4096) {
        int gi = blockIdx.x * 256 + threadIdx.x;   // 4 * 262144
        int s = gi >> 18;
        int i = gi & 262143;
        const float *w, *b, *g, *beta, *mu, *var;
        __half *wf;
        float* bias;
        if (s == 0) { w=w0;b=b0;g=g0;beta=be0;mu=mu0;var=va0; wf=g_wq;bias=g_bq; }
        else if (s == 1) { w=w1;b=b1;g=g1;beta=be1;mu=mu1;var=va1; wf=g_wk;bias=g_bk; }
        else if (s == 2) { w=w2;b=b2;g=g2;beta=be2;mu=mu2;var=va2; wf=g_wv;bias=g_bv; }
        else { w=w3;b=b3;g=g3;beta=be3;mu=mu3;var=va3; wf=g_wp;bias=g_bp; }
        int d = i >> 9;
        float sc = g[d] * rsqrtf(var[d] + EPS_BN);
        wf[i] = __float2half_rn(w[i] * sc);
        if ((i & 511) == 0) bias[d] = (b[d] - mu[d]) * sc + beta[d];
    } else {
        int i = (blockIdx.x - 4096) * 256 + threadIdx.x;   // over 1M float4
        float4 v = ((const float4*)x)[i];
        __half2 a; a.x = __float2half_rn(v.x); a.y = __float2half_rn(v.y);
        __half2 b; b.x = __float2half_rn(v.z); b.y = __float2half_rn(v.w);
        ((__half2*)g_xf)[i * 2 + 0] = a;
        ((__half2*)g_xf)[i * 2 + 1] = b;
    }
}

// ============================ HMMA GEMM v7 (fp16, 1-product): C = relu(A@W^T + bias) ==========
// 128x128 CTA tile, BK=32, 256 threads (8 warps 2m x 4n, 64x32 warp tiles), 2-stage cp.async,
// 2 operand tiles per stage [Af, Wf], 2 CTAs/SM.
#define BK 32
#define NSTAGE (CDIM / BK)          // 16
#define RPITCH 80                   // 64B data + 16B pad
#define T_TB (128 * RPITCH)         // 10240 per operand tile
#define STAGEB (2 * T_TB)           // 20480: [Af, Wf]
#define GEMM_SMEM (2 * STAGEB)      // 40960

__global__ __launch_bounds__(256, 2)
void gemm_tc(float* __restrict__ Cext, int mode)
{
    extern __shared__ char smem[];
    const __half *Af, *Wf;
    const float* bias;
    float* C;
    int bn;
    if (mode == 0) {
        int sel = blockIdx.x >> 2;          // 0=q, 1=k, 2=v
        bn = (blockIdx.x & 3) * 128;
        Af = g_xf;
        Wf = (sel == 0) ? g_wq : (sel == 1) ? g_wk : g_wv;
        bias = (sel == 0) ? g_bq : (sel == 1) ? g_bk : g_bv;
        C = (sel == 0) ? g_q : (sel == 1) ? g_k : g_v;
    } else {
        bn = blockIdx.x * 128;
        Af = g_attf;
        Wf = g_wp; bias = g_bp;
        C = Cext;
    }
    const int bm = blockIdx.y * 128;

    const uint32_t sb = smem_u32(smem);
    const int tid = threadIdx.x;
    const int wid = tid >> 5, lane = tid & 31;
    const int wm = wid & 1, wn = wid >> 1;   // 2(m) x 4(n), 64x32 per warp

    const __half* srcA = Af + (size_t)bm * CDIM;
    const __half* srcW = Wf + (size_t)bn * CDIM;

    // 1024 16B-chunks per stage (2 tensors x 512), 4 per thread
    auto load_stage = [&](int s, int buf) {
        uint32_t sbase = sb + buf * STAGEB;
        int kof = s * BK;
#pragma unroll
        for (int t = 0; t < 4; ++t) {
            int idx = tid + t * 256;
            int ten = idx >> 9;              // 0=Af 1=Wf
            int v = idx & 511;
            int row = v >> 2, ch = v & 3;
            const __half* g = (ten == 0 ? srcA : srcW) + (size_t)row * CDIM + kof + ch * 8;
            cp16(sbase + ten * T_TB + row * RPITCH + ch * 16, g);
        }
        cp_commit();
    };

    float acc[4][4][4];
#pragma unroll
    for (int i = 0; i < 4; ++i)
#pragma unroll
        for (int j = 0; j < 4; ++j)
#pragma unroll
            for (int k = 0; k < 4; ++k) acc[i][j][k] = 0.f;

    const int g8 = lane >> 3, l8 = lane & 7;
    const int a_row = (g8 & 1) * 8 + l8;
    const int a_k = (g8 >> 1) * 8;
    const int w_row = (g8 >> 1) * 8 + l8;
    const int w_k = (g8 & 1) * 8;

    const uint32_t aoffL = (wm * 64 + a_row) * RPITCH + a_k * 2;
    const uint32_t woffL = (wn * 32 + w_row) * RPITCH + w_k * 2;

    load_stage(0, 0);

    for (int s = 0; s < NSTAGE; ++s) {
        cp_wait<0>();
        __syncthreads();
        if (s + 1 < NSTAGE) load_stage(s + 1, (s + 1) & 1);

        const uint32_t base = sb + (s & 1) * STAGEB;
        const uint32_t aB = base + aoffL;
        const uint32_t wB = base + T_TB + woffL;

#pragma unroll
        for (int kk = 0; kk < BK; kk += 16) {
            uint32_t whf[2][4];
            ldsm4(whf[0], wB + kk * 2);
            ldsm4(whf[1], wB + 16 * RPITCH + kk * 2);
            uint32_t ahf[2][4];
            ldsm4(ahf[0], aB + kk * 2);
#pragma unroll
            for (int mi = 0; mi < 4; ++mi) {
                const int cur = mi & 1;
                if (mi < 3) ldsm4(ahf[cur ^ 1], aB + (mi + 1) * (16 * RPITCH) + kk * 2);
#pragma unroll
                for (int nj = 0; nj < 4; ++nj)
                    mma_f16(acc[mi][nj], ahf[cur], whf[nj >> 1][(nj & 1) * 2], whf[nj >> 1][(nj & 1) * 2 + 1]);
            }
        }
    }

    const int r_in = lane >> 2;
    const int c_in = (lane & 3) * 2;
#pragma unroll
    for (int mi = 0; mi < 4; ++mi) {
        int r0 = bm + wm * 64 + mi * 16 + r_in;
#pragma unroll
        for (int nj = 0; nj < 4; ++nj) {
            int c0 = bn + wn * 32 + nj * 8 + c_in;
            float b0 = bias[c0], b1 = bias[c0 + 1];
            float2 lo, hi;
            lo.x = fmaxf(acc[mi][nj][0] + b0, 0.f);
            lo.y = fmaxf(acc[mi][nj][1] + b1, 0.f);
            hi.x = fmaxf(acc[mi][nj][2] + b0, 0.f);
            hi.y = fmaxf(acc[mi][nj][3] + b1, 0.f);
            *(float2*)(C + (size_t)r0 * CDIM + c0) = lo;
            *(float2*)(C + (size_t)(r0 + 8) * CDIM + c0) = hi;
        }
    }
}

// ============================ attention middle ============================
__global__ __launch_bounds__(128)
void kv_outer_partial()
{
    int bh = blockIdx.x, part = blockIdx.y;
    int b = bh >> 3, h = bh & 7;
    __shared__ float Ks[32][64];
    __shared__ float Vs[32][64];
    int tid = threadIdx.x;
    int tx = tid & 15;                // e-group: 4 per thread
    int ty = tid >> 4;                // d-group: 8 per thread
    const float* kbase = g_k + ((size_t)b * 1024) * CDIM + h * 64;
    const float* vbase = g_v + ((size_t)b * 1024) * CDIM + h * 64;

    float acc[8][4];
#pragma unroll
    for (int i = 0; i < 8; ++i)
#pragma unroll
        for (int j = 0; j < 4; ++j) acc[i][j] = 0.f;

    int nbeg = part * 128;
    for (int n0 = nbeg; n0 < nbeg + 128; n0 += 32) {
#pragma unroll
        for (int u = 0; u < 4; ++u) {
            int v = tid + u * 128;
            int r = v >> 4, c4 = v & 15;
            *(float4*)&Ks[r][c4 * 4] = *(const float4*)(kbase + (size_t)(n0 + r) * CDIM + c4 * 4);
            *(float4*)&Vs[r][c4 * 4] = *(const float4*)(vbase + (size_t)(n0 + r) * CDIM + c4 * 4);
        }
        __syncthreads();
#pragma unroll
        for (int nn = 0; nn < 32; ++nn) {
            float4 k0 = *(const float4*)&Ks[nn][ty * 8];
            float4 k1 = *(const float4*)&Ks[nn][ty * 8 + 4];
            float4 vv = *(const float4*)&Vs[nn][tx * 4];
            float ka[8] = {k0.x, k0.y, k0.z, k0.w, k1.x, k1.y, k1.z, k1.w};
            float va[4] = {vv.x, vv.y, vv.z, vv.w};
#pragma unroll
            for (int i = 0; i < 8; ++i)
#pragma unroll
                for (int j = 0; j < 4; ++j)
                    acc[i][j] = fmaf(ka[i], va[j], acc[i][j]);
        }
        __syncthreads();
    }

    float* mp = g_mpart + ((size_t)part * 64 + bh) * 4096;
#pragma unroll
    for (int i = 0; i < 8; ++i) {
        float* row = mp + (ty * 8 + i) * 64 + tx * 4;
        float4 o = {acc[i][0], acc[i][1], acc[i][2], acc[i][3]};
        *(float4*)row = o;
    }
}

__global__ void kv_reduce8()
{
    int i = blockIdx.x * blockDim.x + threadIdx.x;   // over 65536 float4
    float4 s = ((const float4*)g_mpart)[i];
#pragma unroll
    for (int p = 1; p < 8; ++p) {
        float4 t = ((const float4*)g_mpart)[p * 65536 + i];
        s.x += t.x; s.y += t.y; s.z += t.z; s.w += t.w;
    }
    s.x *= SCALE_ATTN; s.y *= SCALE_ATTN; s.z *= SCALE_ATTN; s.w *= SCALE_ATTN;
    ((float4*)g_m)[i] = s;
}

// att = relu(q @ M) -> single fp16
__global__ __launch_bounds__(256)
void qm_relu_split()
{
    int nt = blockIdx.x, h = blockIdx.y, b = blockIdx.z;
    __shared__ float Qs[64][65];
    __shared__ float Ms[64][68];
    int tid = threadIdx.x;
    const float* qbase = g_q + ((size_t)(b * 1024 + nt * 64)) * CDIM + h * 64;
    const float* mbase = g_m + (size_t)(b * 8 + h) * 4096;
#pragma unroll
    for (int u = 0; u < 4; ++u) {
        int v = tid + u * 256;
        int r = v >> 4, c4 = v & 15;
        float4 t = *(const float4*)(qbase + (size_t)r * CDIM + c4 * 4);
        Qs[r][c4 * 4 + 0] = t.x; Qs[r][c4 * 4 + 1] = t.y;
        Qs[r][c4 * 4 + 2] = t.z; Qs[r][c4 * 4 + 3] = t.w;
        *(float4*)&Ms[r][c4 * 4] = *(const float4*)(mbase + r * 64 + c4 * 4);
    }
    __syncthreads();
    int r = tid >> 2, quarter = tid & 3;
    float acc[16];
#pragma unroll
    for (int e = 0; e < 16; ++e) acc[e] = 0.f;
#pragma unroll
    for (int d = 0; d < 64; ++d) {
        float qv = Qs[r][d];
#pragma unroll
        for (int e4 = 0; e4 < 4; ++e4) {
            float4 m = *(const float4*)&Ms[d][quarter * 16 + e4 * 4];
            acc[e4 * 4 + 0] = fmaf(qv, m.x, acc[e4 * 4 + 0]);
            acc[e4 * 4 + 1] = fmaf(qv, m.y, acc[e4 * 4 + 1]);
            acc[e4 * 4 + 2] = fmaf(qv, m.z, acc[e4 * 4 + 2]);
            acc[e4 * 4 + 3] = fmaf(qv, m.w, acc[e4 * 4 + 3]);
        }
    }
    size_t obase = ((size_t)(b * 1024 + nt * 64 + r)) * CDIM + h * 64 + quarter * 16;
#pragma unroll
    for (int e2 = 0; e2 < 8; ++e2) {
        __half2 hh;
        hh.x = __float2half_rn(fmaxf(acc[e2 * 2 + 0], 0.f));
        hh.y = __float2half_rn(fmaxf(acc[e2 * 2 + 1], 0.f));
        *(__half2*)(g_attf + obase + e2 * 2) = hh;
    }
}

// ============================ host launch ============================
extern "C" void kernel_launch(void* const* d_in, const int* in_sizes, int n_in,
                              void* d_out, int out_size)
{
    (void)in_sizes; (void)n_in; (void)out_size;
    const float* x = (const float*)d_in[0];
    const float** p = (const float**)(d_in + 1);   // 24 params: 4 sets x 6

    cudaFuncSetAttribute(gemm_tc, cudaFuncAttributeMaxDynamicSharedMemorySize, GEMM_SMEM);

    prep_all<<<8192, 256>>>(x,
        p[0], p[1], p[2], p[3], p[4], p[5],
        p[6], p[7], p[8], p[9], p[10], p[11],
        p[12], p[13], p[14], p[15], p[16], p[17],
        p[18], p[19], p[20], p[21], p[22], p[23]);

    // fused QKV: grid (12, 64) = 768 CTAs, 256 thr, 2 CTAs/SM
    gemm_tc<<<dim3(12, 64), 256, GEMM_SMEM>>>(nullptr, 0);

    kv_outer_partial<<<dim3(64, 8), 128>>>();
    kv_reduce8<<<512, 128>>>();
    qm_relu_split<<<dim3(16, 8, 8), 256>>>();

    // P projection
    gemm_tc<<<dim3(4, 64), 256, GEMM_SMEM>>>((float*)d_out, 1);
}

// round 11
// speedup vs baseline: 1.5695x; 1.0132x over previous
#include <cuda_runtime.h>
#include <cuda_fp16.h>
#include <cstdint>

#define EPS_BN 1e-5f
#define SCALE_ATTN 0.125f
#define CDIM 512
#define MROWS 8192   // B*N

// ============================ scratch (static device mem) ============================
__device__ __align__(16) __half g_xf[MROWS*CDIM];
__device__ __align__(16) __half g_attf[MROWS*CDIM];
__device__ __align__(16) __half g_wq[CDIM*CDIM], g_wk[CDIM*CDIM];
__device__ __align__(16) __half g_wv[CDIM*CDIM], g_wp[CDIM*CDIM];
__device__ float g_bq[CDIM], g_bk[CDIM], g_bv[CDIM], g_bp[CDIM];
__device__ __align__(16) __half g_q[MROWS*CDIM], g_k[MROWS*CDIM], g_v[MROWS*CDIM];
__device__ __align__(16) float g_m[64*64*64];
__device__ __align__(16) float g_mpart[8*64*64*64];   // 8 partials

// ============================ portable PTX helpers ============================
__device__ __forceinline__ uint32_t smem_u32(const void* p) {
    uint32_t a;
    asm("{ .reg .u64 t; cvta.to.shared.u64 t, %1; cvt.u32.u64 %0, t; }" : "=r"(a) : "l"(p));
    return a;
}
__device__ __forceinline__ void cp16(uint32_t saddr, const void* g) {
    asm volatile("cp.async.cg.shared.global [%0], [%1], 16;" :: "r"(saddr), "l"(g) : "memory");
}
__device__ __forceinline__ void cp_commit() {
    asm volatile("cp.async.commit_group;" ::: "memory");
}
template <int N> __device__ __forceinline__ void cp_wait() {
    asm volatile("cp.async.wait_group %0;" :: "n"(N) : "memory");
}
__device__ __forceinline__ void ldsm4(uint32_t* r, uint32_t addr) {
    asm volatile("ldmatrix.sync.aligned.m8n8.x4.shared.b16 {%0,%1,%2,%3}, [%4];"
                 : "=r"(r[0]), "=r"(r[1]), "=r"(r[2]), "=r"(r[3]) : "r"(addr));
}
__device__ __forceinline__ void mma_f16(float* c, const uint32_t* a, uint32_t b0, uint32_t b1) {
    asm volatile(
        "mma.sync.aligned.m16n8k16.row.col.f32.f16.f16.f32 "
        "{%0,%1,%2,%3}, {%4,%5,%6,%7}, {%8,%9}, {%0,%1,%2,%3};"
        : "+f"(c[0]), "+f"(c[1]), "+f"(c[2]), "+f"(c[3])
        : "r"(a[0]), "r"(a[1]), "r"(a[2]), "r"(a[3]), "r"(b0), "r"(b1));
}
// load 8 halves (16B) and convert to 8 floats
__device__ __forceinline__ void ld8h_to_f(const __half* g, float* out) {
    uint4 raw = *(const uint4*)g;
    const __half2* hp = (const __half2*)&raw;
#pragma unroll
    for (int i = 0; i < 4; ++i) {
        float2 f = __half22float2(hp[i]);
        out[i * 2 + 0] = f.x;
        out[i * 2 + 1] = f.y;
    }
}

// ============================ fused prep: BN-fold all 4 sets + x->fp16 ============================
__global__ void prep_all(
    const float* __restrict__ x,
    const float* __restrict__ w0, const float* __restrict__ b0, const float* __restrict__ g0,
    const float* __restrict__ be0, const float* __restrict__ mu0, const float* __restrict__ va0,
    const float* __restrict__ w1, const float* __restrict__ b1, const float* __restrict__ g1,
    const float* __restrict__ be1, const float* __restrict__ mu1, const float* __restrict__ va1,
    const float* __restrict__ w2, const float* __restrict__ b2, const float* __restrict__ g2,
    const float* __restrict__ be2, const float* __restrict__ mu2, const float* __restrict__ va2,
    const float* __restrict__ w3, const float* __restrict__ b3, const float* __restrict__ g3,
    const float* __restrict__ be3, const float* __restrict__ mu3, const float* __restrict__ va3)
{
    if (blockIdx.x < 4096) {
        int gi = blockIdx.x * 256 + threadIdx.x;   // 4 * 262144
        int s = gi >> 18;
        int i = gi & 262143;
        const float *w, *b, *g, *beta, *mu, *var;
        __half *wf;
        float* bias;
        if (s == 0) { w=w0;b=b0;g=g0;beta=be0;mu=mu0;var=va0; wf=g_wq;bias=g_bq; }
        else if (s == 1) { w=w1;b=b1;g=g1;beta=be1;mu=mu1;var=va1; wf=g_wk;bias=g_bk; }
        else if (s == 2) { w=w2;b=b2;g=g2;beta=be2;mu=mu2;var=va2; wf=g_wv;bias=g_bv; }
        else { w=w3;b=b3;g=g3;beta=be3;mu=mu3;var=va3; wf=g_wp;bias=g_bp; }
        int d = i >> 9;
        float sc = g[d] * rsqrtf(var[d] + EPS_BN);
        wf[i] = __float2half_rn(w[i] * sc);
        if ((i & 511) == 0) bias[d] = (b[d] - mu[d]) * sc + beta[d];
    } else {
        int i = (blockIdx.x - 4096) * 256 + threadIdx.x;   // over 1M float4
        float4 v = ((const float4*)x)[i];
        __half2 a; a.x = __float2half_rn(v.x); a.y = __float2half_rn(v.y);
        __half2 b; b.x = __float2half_rn(v.z); b.y = __float2half_rn(v.w);
        ((__half2*)g_xf)[i * 2 + 0] = a;
        ((__half2*)g_xf)[i * 2 + 1] = b;
    }
}

// ============================ HMMA GEMM (fp16, 1-product): C = relu(A@W^T + bias) ==========
// 128x128 CTA tile, BK=32, 256 threads (8 warps 2m x 4n, 64x32 warp tiles), 2-stage cp.async.
// mode 0: fused QKV from xf, OUTPUT fp16 (q/k/v). mode 1: P from attf, OUTPUT fp32 (d_out).
#define BK 32
#define NSTAGE (CDIM / BK)          // 16
#define RPITCH 80                   // 64B data + 16B pad
#define T_TB (128 * RPITCH)         // 10240 per operand tile
#define STAGEB (2 * T_TB)           // 20480: [Af, Wf]
#define GEMM_SMEM (2 * STAGEB)      // 40960

__global__ __launch_bounds__(256, 2)
void gemm_tc(float* __restrict__ Cext, int mode)
{
    extern __shared__ char smem[];
    const __half *Af, *Wf;
    const float* bias;
    __half* Ch = nullptr;
    float* Cf = nullptr;
    int bn;
    if (mode == 0) {
        int sel = blockIdx.x >> 2;          // 0=q, 1=k, 2=v
        bn = (blockIdx.x & 3) * 128;
        Af = g_xf;
        Wf = (sel == 0) ? g_wq : (sel == 1) ? g_wk : g_wv;
        bias = (sel == 0) ? g_bq : (sel == 1) ? g_bk : g_bv;
        Ch = (sel == 0) ? g_q : (sel == 1) ? g_k : g_v;
    } else {
        bn = blockIdx.x * 128;
        Af = g_attf;
        Wf = g_wp; bias = g_bp;
        Cf = Cext;
    }
    const int bm = blockIdx.y * 128;

    const uint32_t sb = smem_u32(smem);
    const int tid = threadIdx.x;
    const int wid = tid >> 5, lane = tid & 31;
    const int wm = wid & 1, wn = wid >> 1;   // 2(m) x 4(n), 64x32 per warp

    const __half* srcA = Af + (size_t)bm * CDIM;
    const __half* srcW = Wf + (size_t)bn * CDIM;

    auto load_stage = [&](int s, int buf) {
        uint32_t sbase = sb + buf * STAGEB;
        int kof = s * BK;
#pragma unroll
        for (int t = 0; t < 4; ++t) {
            int idx = tid + t * 256;
            int ten = idx >> 9;              // 0=Af 1=Wf
            int v = idx & 511;
            int row = v >> 2, ch = v & 3;
            const __half* g = (ten == 0 ? srcA : srcW) + (size_t)row * CDIM + kof + ch * 8;
            cp16(sbase + ten * T_TB + row * RPITCH + ch * 16, g);
        }
        cp_commit();
    };

    float acc[4][4][4];
#pragma unroll
    for (int i = 0; i < 4; ++i)
#pragma unroll
        for (int j = 0; j < 4; ++j)
#pragma unroll
            for (int k = 0; k < 4; ++k) acc[i][j][k] = 0.f;

    const int g8 = lane >> 3, l8 = lane & 7;
    const int a_row = (g8 & 1) * 8 + l8;
    const int a_k = (g8 >> 1) * 8;
    const int w_row = (g8 >> 1) * 8 + l8;
    const int w_k = (g8 & 1) * 8;

    const uint32_t aoffL = (wm * 64 + a_row) * RPITCH + a_k * 2;
    const uint32_t woffL = (wn * 32 + w_row) * RPITCH + w_k * 2;

    load_stage(0, 0);

    for (int s = 0; s < NSTAGE; ++s) {
        cp_wait<0>();
        __syncthreads();
        if (s + 1 < NSTAGE) load_stage(s + 1, (s + 1) & 1);

        const uint32_t base = sb + (s & 1) * STAGEB;
        const uint32_t aB = base + aoffL;
        const uint32_t wB = base + T_TB + woffL;

#pragma unroll
        for (int kk = 0; kk < BK; kk += 16) {
            uint32_t whf[2][4];
            ldsm4(whf[0], wB + kk * 2);
            ldsm4(whf[1], wB + 16 * RPITCH + kk * 2);
            uint32_t ahf[2][4];
            ldsm4(ahf[0], aB + kk * 2);
#pragma unroll
            for (int mi = 0; mi < 4; ++mi) {
                const int cur = mi & 1;
                if (mi < 3) ldsm4(ahf[cur ^ 1], aB + (mi + 1) * (16 * RPITCH) + kk * 2);
#pragma unroll
                for (int nj = 0; nj < 4; ++nj)
                    mma_f16(acc[mi][nj], ahf[cur], whf[nj >> 1][(nj & 1) * 2], whf[nj >> 1][(nj & 1) * 2 + 1]);
            }
        }
    }

    const int r_in = lane >> 2;
    const int c_in = (lane & 3) * 2;
#pragma unroll
    for (int mi = 0; mi < 4; ++mi) {
        int r0 = bm + wm * 64 + mi * 16 + r_in;
#pragma unroll
        for (int nj = 0; nj < 4; ++nj) {
            int c0 = bn + wn * 32 + nj * 8 + c_in;
            float b0 = bias[c0], b1 = bias[c0 + 1];
            float v00 = fmaxf(acc[mi][nj][0] + b0, 0.f);
            float v01 = fmaxf(acc[mi][nj][1] + b1, 0.f);
            float v10 = fmaxf(acc[mi][nj][2] + b0, 0.f);
            float v11 = fmaxf(acc[mi][nj][3] + b1, 0.f);
            if (mode == 0) {
                __half2 lo; lo.x = __float2half_rn(v00); lo.y = __float2half_rn(v01);
                __half2 hi; hi.x = __float2half_rn(v10); hi.y = __float2half_rn(v11);
                *(__half2*)(Ch + (size_t)r0 * CDIM + c0) = lo;
                *(__half2*)(Ch + (size_t)(r0 + 8) * CDIM + c0) = hi;
            } else {
                float2 lo = {v00, v01};
                float2 hi = {v10, v11};
                *(float2*)(Cf + (size_t)r0 * CDIM + c0) = lo;
                *(float2*)(Cf + (size_t)(r0 + 8) * CDIM + c0) = hi;
            }
        }
    }
}

// ============================ attention middle ============================
// kv_outer: per (bh, part) accumulate K^T V over 128 rows; k,v are fp16 now.
__global__ __launch_bounds__(128)
void kv_outer_partial()
{
    int bh = blockIdx.x, part = blockIdx.y;
    int b = bh >> 3, h = bh & 7;
    __shared__ float Ks[32][64];
    __shared__ float Vs[32][64];
    int tid = threadIdx.x;
    int tx = tid & 15;                // e-group: 4 per thread
    int ty = tid >> 4;                // d-group: 8 per thread
    const __half* kbase = g_k + ((size_t)b * 1024) * CDIM + h * 64;
    const __half* vbase = g_v + ((size_t)b * 1024) * CDIM + h * 64;

    float acc[8][4];
#pragma unroll
    for (int i = 0; i < 8; ++i)
#pragma unroll
        for (int j = 0; j < 4; ++j) acc[i][j] = 0.f;

    int nbeg = part * 128;
    for (int n0 = nbeg; n0 < nbeg + 128; n0 += 32) {
        // 32 rows x 64 halves = 256 chunks of 8 halves; 128 threads -> 2 each
#pragma unroll
        for (int u = 0; u < 2; ++u) {
            int v = tid + u * 128;
            int r = v >> 3, c8 = v & 7;
            ld8h_to_f(kbase + (size_t)(n0 + r) * CDIM + c8 * 8, &Ks[r][c8 * 8]);
            ld8h_to_f(vbase + (size_t)(n0 + r) * CDIM + c8 * 8, &Vs[r][c8 * 8]);
        }
        __syncthreads();
#pragma unroll
        for (int nn = 0; nn < 32; ++nn) {
            float4 k0 = *(const float4*)&Ks[nn][ty * 8];
            float4 k1 = *(const float4*)&Ks[nn][ty * 8 + 4];
            float4 vv = *(const float4*)&Vs[nn][tx * 4];
            float ka[8] = {k0.x, k0.y, k0.z, k0.w, k1.x, k1.y, k1.z, k1.w};
            float va[4] = {vv.x, vv.y, vv.z, vv.w};
#pragma unroll
            for (int i = 0; i < 8; ++i)
#pragma unroll
                for (int j = 0; j < 4; ++j)
                    acc[i][j] = fmaf(ka[i], va[j], acc[i][j]);
        }
        __syncthreads();
    }

    float* mp = g_mpart + ((size_t)part * 64 + bh) * 4096;
#pragma unroll
    for (int i = 0; i < 8; ++i) {
        float* row = mp + (ty * 8 + i) * 64 + tx * 4;
        float4 o = {acc[i][0], acc[i][1], acc[i][2], acc[i][3]};
        *(float4*)row = o;
    }
}

__global__ void kv_reduce8()
{
    int i = blockIdx.x * blockDim.x + threadIdx.x;   // over 65536 float4
    float4 s = ((const float4*)g_mpart)[i];
#pragma unroll
    for (int p = 1; p < 8; ++p) {
        float4 t = ((const float4*)g_mpart)[p * 65536 + i];
        s.x += t.x; s.y += t.y; s.z += t.z; s.w += t.w;
    }
    s.x *= SCALE_ATTN; s.y *= SCALE_ATTN; s.z *= SCALE_ATTN; s.w *= SCALE_ATTN;
    ((float4*)g_m)[i] = s;
}

// att = relu(q @ M) -> fp16; q is fp16 now
__global__ __launch_bounds__(256)
void qm_relu_split()
{
    int nt = blockIdx.x, h = blockIdx.y, b = blockIdx.z;
    __shared__ float Qs[64][65];
    __shared__ float Ms[64][68];
    int tid = threadIdx.x;
    const __half* qbase = g_q + ((size_t)(b * 1024 + nt * 64)) * CDIM + h * 64;
    const float* mbase = g_m + (size_t)(b * 8 + h) * 4096;
    // q: 64 rows x 64 halves = 512 chunks of 8 halves; 256 threads -> 2 each
#pragma unroll
    for (int u = 0; u < 2; ++u) {
        int idx = tid + u * 256;
        int r = idx >> 3, c8 = idx & 7;
        ld8h_to_f(qbase + (size_t)r * CDIM + c8 * 8, &Qs[r][c8 * 8]);
    }
    // m: 64 rows x 64 floats = 1024 float4; 256 threads -> 4 each
#pragma unroll
    for (int u = 0; u < 4; ++u) {
        int idx = tid + u * 256;
        int r = idx >> 4, c4 = idx & 15;
        *(float4*)&Ms[r][c4 * 4] = *(const float4*)(mbase + r * 64 + c4 * 4);
    }
    __syncthreads();
    int r = tid >> 2, quarter = tid & 3;
    float acc[16];
#pragma unroll
    for (int e = 0; e < 16; ++e) acc[e] = 0.f;
#pragma unroll
    for (int d = 0; d < 64; ++d) {
        float qv = Qs[r][d];
#pragma unroll
        for (int e4 = 0; e4 < 4; ++e4) {
            float4 m = *(const float4*)&Ms[d][quarter * 16 + e4 * 4];
            acc[e4 * 4 + 0] = fmaf(qv, m.x, acc[e4 * 4 + 0]);
            acc[e4 * 4 + 1] = fmaf(qv, m.y, acc[e4 * 4 + 1]);
            acc[e4 * 4 + 2] = fmaf(qv, m.z, acc[e4 * 4 + 2]);
            acc[e4 * 4 + 3] = fmaf(qv, m.w, acc[e4 * 4 + 3]);
        }
    }
    size_t obase = ((size_t)(b * 1024 + nt * 64 + r)) * CDIM + h * 64 + quarter * 16;
#pragma unroll
    for (int e2 = 0; e2 < 8; ++e2) {
        __half2 hh;
        hh.x = __float2half_rn(fmaxf(acc[e2 * 2 + 0], 0.f));
        hh.y = __float2half_rn(fmaxf(acc[e2 * 2 + 1], 0.f));
        *(__half2*)(g_attf + obase + e2 * 2) = hh;
    }
}

// ============================ host launch ============================
extern "C" void kernel_launch(void* const* d_in, const int* in_sizes, int n_in,
                              void* d_out, int out_size)
{
    (void)in_sizes; (void)n_in; (void)out_size;
    const float* x = (const float*)d_in[0];
    const float** p = (const float**)(d_in + 1);   // 24 params: 4 sets x 6

    cudaFuncSetAttribute(gemm_tc, cudaFuncAttributeMaxDynamicSharedMemorySize, GEMM_SMEM);

    prep_all<<<8192, 256>>>(x,
        p[0], p[1], p[2], p[3], p[4], p[5],
        p[6], p[7], p[8], p[9], p[10], p[11],
        p[12], p[13], p[14], p[15], p[16], p[17],
        p[18], p[19], p[20], p[21], p[22], p[23]);

    // fused QKV: grid (12, 64) = 768 CTAs, 256 thr, 2 CTAs/SM
    gemm_tc<<<dim3(12, 64), 256, GEMM_SMEM>>>(nullptr, 0);

    kv_outer_partial<<<dim3(64, 8), 128>>>();
    kv_reduce8<<<512, 128>>>();
    qm_relu_split<<<dim3(16, 8, 8), 256>>>();

    // P projection
    gemm_tc<<<dim3(4, 64), 256, GEMM_SMEM>>>((float*)d_out, 1);
}

// round 12
// speedup vs baseline: 1.6296x; 1.0383x over previous
#include <cuda_runtime.h>
#include <cuda_fp16.h>
#include <cstdint>

#define EPS_BN 1e-5f
#define SCALE_ATTN 0.125f
#define CDIM 512
#define MROWS 8192   // B*N

// ============================ scratch (static device mem) ============================
__device__ __align__(16) __half g_xf[MROWS*CDIM];
__device__ __align__(16) __half g_attf[MROWS*CDIM];
__device__ __align__(16) __half g_wq[CDIM*CDIM], g_wk[CDIM*CDIM];
__device__ __align__(16) __half g_wv[CDIM*CDIM], g_wp[CDIM*CDIM];
__device__ float g_bq[CDIM], g_bk[CDIM], g_bv[CDIM], g_bp[CDIM];
__device__ __align__(16) __half g_q[MROWS*CDIM], g_k[MROWS*CDIM], g_v[MROWS*CDIM];
__device__ __align__(16) float g_m[64*64*64];    // accumulated via atomics

// ============================ portable PTX helpers ============================
__device__ __forceinline__ uint32_t smem_u32(const void* p) {
    uint32_t a;
    asm("{ .reg .u64 t; cvta.to.shared.u64 t, %1; cvt.u32.u64 %0, t; }" : "=r"(a) : "l"(p));
    return a;
}
__device__ __forceinline__ void cp16(uint32_t saddr, const void* g) {
    asm volatile("cp.async.cg.shared.global [%0], [%1], 16;" :: "r"(saddr), "l"(g) : "memory");
}
__device__ __forceinline__ void cp_commit() {
    asm volatile("cp.async.commit_group;" ::: "memory");
}
template <int N> __device__ __forceinline__ void cp_wait() {
    asm volatile("cp.async.wait_group %0;" :: "n"(N) : "memory");
}
__device__ __forceinline__ void ldsm4(uint32_t* r, uint32_t addr) {
    asm volatile("ldmatrix.sync.aligned.m8n8.x4.shared.b16 {%0,%1,%2,%3}, [%4];"
                 : "=r"(r[0]), "=r"(r[1]), "=r"(r[2]), "=r"(r[3]) : "r"(addr));
}
__device__ __forceinline__ void mma_f16(float* c, const uint32_t* a, uint32_t b0, uint32_t b1) {
    asm volatile(
        "mma.sync.aligned.m16n8k16.row.col.f32.f16.f16.f32 "
        "{%0,%1,%2,%3}, {%4,%5,%6,%7}, {%8,%9}, {%0,%1,%2,%3};"
        : "+f"(c[0]), "+f"(c[1]), "+f"(c[2]), "+f"(c[3])
        : "r"(a[0]), "r"(a[1]), "r"(a[2]), "r"(a[3]), "r"(b0), "r"(b1));
}
// load 8 halves (16B) and convert to 8 floats
__device__ __forceinline__ void ld8h_to_f(const __half* g, float* out) {
    uint4 raw = *(const uint4*)g;
    const __half2* hp = (const __half2*)&raw;
#pragma unroll
    for (int i = 0; i < 4; ++i) {
        float2 f = __half22float2(hp[i]);
        out[i * 2 + 0] = f.x;
        out[i * 2 + 1] = f.y;
    }
}

// ============================ fused prep: BN-fold + x->fp16 + zero g_m ============================
// blocks [0,4096): fold 4x262144 weight elems -> fp16.
// blocks [4096,8192): x -> fp16 (1M float4).
// blocks [8192,8224): zero g_m (65536 float4 over 8192 threads -> 8 each).
__global__ void prep_all(
    const float* __restrict__ x,
    const float* __restrict__ w0, const float* __restrict__ b0, const float* __restrict__ g0,
    const float* __restrict__ be0, const float* __restrict__ mu0, const float* __restrict__ va0,
    const float* __restrict__ w1, const float* __restrict__ b1, const float* __restrict__ g1,
    const float* __restrict__ be1, const float* __restrict__ mu1, const float* __restrict__ va1,
    const float* __restrict__ w2, const float* __restrict__ b2, const float* __restrict__ g2,
    const float* __restrict__ be2, const float* __restrict__ mu2, const float* __restrict__ va2,
    const float* __restrict__ w3, const float* __restrict__ b3, const float* __restrict__ g3,
    const float* __restrict__ be3, const float* __restrict__ mu3, const float* __restrict__ va3)
{
    if (blockIdx.x < 4096) {
        int gi = blockIdx.x * 256 + threadIdx.x;   // 4 * 262144
        int s = gi >> 18;
        int i = gi & 262143;
        const float *w, *b, *g, *beta, *mu, *var;
        __half *wf;
        float* bias;
        if (s == 0) { w=w0;b=b0;g=g0;beta=be0;mu=mu0;var=va0; wf=g_wq;bias=g_bq; }
        else if (s == 1) { w=w1;b=b1;g=g1;beta=be1;mu=mu1;var=va1; wf=g_wk;bias=g_bk; }
        else if (s == 2) { w=w2;b=b2;g=g2;beta=be2;mu=mu2;var=va2; wf=g_wv;bias=g_bv; }
        else { w=w3;b=b3;g=g3;beta=be3;mu=mu3;var=va3; wf=g_wp;bias=g_bp; }
        int d = i >> 9;
        float sc = g[d] * rsqrtf(var[d] + EPS_BN);
        wf[i] = __float2half_rn(w[i] * sc);
        if ((i & 511) == 0) bias[d] = (b[d] - mu[d]) * sc + beta[d];
    } else if (blockIdx.x < 8192) {
        int i = (blockIdx.x - 4096) * 256 + threadIdx.x;   // over 1M float4
        float4 v = ((const float4*)x)[i];
        __half2 a; a.x = __float2half_rn(v.x); a.y = __float2half_rn(v.y);
        __half2 b; b.x = __float2half_rn(v.z); b.y = __float2half_rn(v.w);
        ((__half2*)g_xf)[i * 2 + 0] = a;
        ((__half2*)g_xf)[i * 2 + 1] = b;
    } else {
        int base = (blockIdx.x - 8192) * 256 + threadIdx.x;   // 8192 threads
        float4 z = {0.f, 0.f, 0.f, 0.f};
#pragma unroll
        for (int u = 0; u < 8; ++u)
            ((float4*)g_m)[base + u * 8192] = z;
    }
}

// ============================ HMMA GEMM (fp16, 1-product, BK=64): C = relu(A@W^T + bias) ======
// 128x128 CTA tile, BK=64, 256 threads (8 warps 2m x 4n, 64x32 warp tiles), 2-stage cp.async.
// mode 0: fused QKV from xf -> fp16 q/k/v. mode 1: P from attf -> fp32 d_out.
#define BK 64
#define NSTAGE (CDIM / BK)          // 8
#define RPITCH 144                  // 128B data + 16B pad
#define T_TB (128 * RPITCH)         // 18432 per operand tile
#define STAGEB (2 * T_TB)           // 36864: [Af, Wf]
#define GEMM_SMEM (2 * STAGEB)      // 73728

__global__ __launch_bounds__(256, 2)
void gemm_tc(float* __restrict__ Cext, int mode)
{
    extern __shared__ char smem[];
    const __half *Af, *Wf;
    const float* bias;
    __half* Ch = nullptr;
    float* Cf = nullptr;
    int bn;
    if (mode == 0) {
        int sel = blockIdx.x >> 2;          // 0=q, 1=k, 2=v
        bn = (blockIdx.x & 3) * 128;
        Af = g_xf;
        Wf = (sel == 0) ? g_wq : (sel == 1) ? g_wk : g_wv;
        bias = (sel == 0) ? g_bq : (sel == 1) ? g_bk : g_bv;
        Ch = (sel == 0) ? g_q : (sel == 1) ? g_k : g_v;
    } else {
        bn = blockIdx.x * 128;
        Af = g_attf;
        Wf = g_wp; bias = g_bp;
        Cf = Cext;
    }
    const int bm = blockIdx.y * 128;

    const uint32_t sb = smem_u32(smem);
    const int tid = threadIdx.x;
    const int wid = tid >> 5, lane = tid & 31;
    const int wm = wid & 1, wn = wid >> 1;   // 2(m) x 4(n), 64x32 per warp

    const __half* srcA = Af + (size_t)bm * CDIM;
    const __half* srcW = Wf + (size_t)bn * CDIM;

    // 2048 16B-chunks per stage (2 tensors x 128 rows x 8 chunks), 8 per thread
    auto load_stage = [&](int s, int buf) {
        uint32_t sbase = sb + buf * STAGEB;
        int kof = s * BK;
#pragma unroll
        for (int t = 0; t < 8; ++t) {
            int idx = tid + t * 256;
            int ten = idx >> 10;             // 0=Af 1=Wf
            int v = idx & 1023;
            int row = v >> 3, ch = v & 7;
            const __half* g = (ten == 0 ? srcA : srcW) + (size_t)row * CDIM + kof + ch * 8;
            cp16(sbase + ten * T_TB + row * RPITCH + ch * 16, g);
        }
        cp_commit();
    };

    float acc[4][4][4];
#pragma unroll
    for (int i = 0; i < 4; ++i)
#pragma unroll
        for (int j = 0; j < 4; ++j)
#pragma unroll
            for (int k = 0; k < 4; ++k) acc[i][j][k] = 0.f;

    const int g8 = lane >> 3, l8 = lane & 7;
    const int a_row = (g8 & 1) * 8 + l8;
    const int a_k = (g8 >> 1) * 8;
    const int w_row = (g8 >> 1) * 8 + l8;
    const int w_k = (g8 & 1) * 8;

    const uint32_t aoffL = (wm * 64 + a_row) * RPITCH + a_k * 2;
    const uint32_t woffL = (wn * 32 + w_row) * RPITCH + w_k * 2;

    load_stage(0, 0);

    for (int s = 0; s < NSTAGE; ++s) {
        cp_wait<0>();
        __syncthreads();
        if (s + 1 < NSTAGE) load_stage(s + 1, (s + 1) & 1);

        const uint32_t base = sb + (s & 1) * STAGEB;
        const uint32_t aB = base + aoffL;
        const uint32_t wB = base + T_TB + woffL;

#pragma unroll
        for (int kk = 0; kk < BK; kk += 16) {
            uint32_t whf[2][4];
            ldsm4(whf[0], wB + kk * 2);
            ldsm4(whf[1], wB + 16 * RPITCH + kk * 2);
            uint32_t ahf[2][4];
            ldsm4(ahf[0], aB + kk * 2);
#pragma unroll
            for (int mi = 0; mi < 4; ++mi) {
                const int cur = mi & 1;
                if (mi < 3) ldsm4(ahf[cur ^ 1], aB + (mi + 1) * (16 * RPITCH) + kk * 2);
#pragma unroll
                for (int nj = 0; nj < 4; ++nj)
                    mma_f16(acc[mi][nj], ahf[cur], whf[nj >> 1][(nj & 1) * 2], whf[nj >> 1][(nj & 1) * 2 + 1]);
            }
        }
    }

    const int r_in = lane >> 2;
    const int c_in = (lane & 3) * 2;
#pragma unroll
    for (int mi = 0; mi < 4; ++mi) {
        int r0 = bm + wm * 64 + mi * 16 + r_in;
#pragma unroll
        for (int nj = 0; nj < 4; ++nj) {
            int c0 = bn + wn * 32 + nj * 8 + c_in;
            float b0 = bias[c0], b1 = bias[c0 + 1];
            float v00 = fmaxf(acc[mi][nj][0] + b0, 0.f);
            float v01 = fmaxf(acc[mi][nj][1] + b1, 0.f);
            float v10 = fmaxf(acc[mi][nj][2] + b0, 0.f);
            float v11 = fmaxf(acc[mi][nj][3] + b1, 0.f);
            if (mode == 0) {
                __half2 lo; lo.x = __float2half_rn(v00); lo.y = __float2half_rn(v01);
                __half2 hi; hi.x = __float2half_rn(v10); hi.y = __float2half_rn(v11);
                *(__half2*)(Ch + (size_t)r0 * CDIM + c0) = lo;
                *(__half2*)(Ch + (size_t)(r0 + 8) * CDIM + c0) = hi;
            } else {
                float2 lo = {v00, v01};
                float2 hi = {v10, v11};
                *(float2*)(Cf + (size_t)r0 * CDIM + c0) = lo;
                *(float2*)(Cf + (size_t)(r0 + 8) * CDIM + c0) = hi;
            }
        }
    }
}

// ============================ attention middle ============================
// kv_outer: per (bh, part) accumulate K^T V over 128 rows, REDG-accumulate into g_m.
__global__ __launch_bounds__(128)
void kv_outer_partial()
{
    int bh = blockIdx.x, part = blockIdx.y;
    int b = bh >> 3, h = bh & 7;
    __shared__ float Ks[32][64];
    __shared__ float Vs[32][64];
    int tid = threadIdx.x;
    int tx = tid & 15;                // e-group: 4 per thread
    int ty = tid >> 4;                // d-group: 8 per thread
    const __half* kbase = g_k + ((size_t)b * 1024) * CDIM + h * 64;
    const __half* vbase = g_v + ((size_t)b * 1024) * CDIM + h * 64;

    float acc[8][4];
#pragma unroll
    for (int i = 0; i < 8; ++i)
#pragma unroll
        for (int j = 0; j < 4; ++j) acc[i][j] = 0.f;

    int nbeg = part * 128;
    for (int n0 = nbeg; n0 < nbeg + 128; n0 += 32) {
#pragma unroll
        for (int u = 0; u < 2; ++u) {
            int v = tid + u * 128;
            int r = v >> 3, c8 = v & 7;
            ld8h_to_f(kbase + (size_t)(n0 + r) * CDIM + c8 * 8, &Ks[r][c8 * 8]);
            ld8h_to_f(vbase + (size_t)(n0 + r) * CDIM + c8 * 8, &Vs[r][c8 * 8]);
        }
        __syncthreads();
#pragma unroll
        for (int nn = 0; nn < 32; ++nn) {
            float4 k0 = *(const float4*)&Ks[nn][ty * 8];
            float4 k1 = *(const float4*)&Ks[nn][ty * 8 + 4];
            float4 vv = *(const float4*)&Vs[nn][tx * 4];
            float ka[8] = {k0.x, k0.y, k0.z, k0.w, k1.x, k1.y, k1.z, k1.w};
            float va[4] = {vv.x, vv.y, vv.z, vv.w};
#pragma unroll
            for (int i = 0; i < 8; ++i)
#pragma unroll
                for (int j = 0; j < 4; ++j)
                    acc[i][j] = fmaf(ka[i], va[j], acc[i][j]);
        }
        __syncthreads();
    }

    float* mdst = g_m + (size_t)bh * 4096;
#pragma unroll
    for (int i = 0; i < 8; ++i) {
        float* row = mdst + (ty * 8 + i) * 64 + tx * 4;
        atomicAdd(row + 0, acc[i][0]);
        atomicAdd(row + 1, acc[i][1]);
        atomicAdd(row + 2, acc[i][2]);
        atomicAdd(row + 3, acc[i][3]);
    }
}

// att = relu(q @ (SCALE * M)) -> fp16
__global__ __launch_bounds__(256)
void qm_relu_split()
{
    int nt = blockIdx.x, h = blockIdx.y, b = blockIdx.z;
    __shared__ float Qs[64][65];
    __shared__ float Ms[64][68];
    int tid = threadIdx.x;
    const __half* qbase = g_q + ((size_t)(b * 1024 + nt * 64)) * CDIM + h * 64;
    const float* mbase = g_m + (size_t)(b * 8 + h) * 4096;
#pragma unroll
    for (int u = 0; u < 2; ++u) {
        int idx = tid + u * 256;
        int r = idx >> 3, c8 = idx & 7;
        ld8h_to_f(qbase + (size_t)r * CDIM + c8 * 8, &Qs[r][c8 * 8]);
    }
#pragma unroll
    for (int u = 0; u < 4; ++u) {
        int idx = tid + u * 256;
        int r = idx >> 4, c4 = idx & 15;
        float4 m = *(const float4*)(mbase + r * 64 + c4 * 4);
        m.x *= SCALE_ATTN; m.y *= SCALE_ATTN; m.z *= SCALE_ATTN; m.w *= SCALE_ATTN;
        *(float4*)&Ms[r][c4 * 4] = m;
    }
    __syncthreads();
    int r = tid >> 2, quarter = tid & 3;
    float acc[16];
#pragma unroll
    for (int e = 0; e < 16; ++e) acc[e] = 0.f;
#pragma unroll
    for (int d = 0; d < 64; ++d) {
        float qv = Qs[r][d];
#pragma unroll
        for (int e4 = 0; e4 < 4; ++e4) {
            float4 m = *(const float4*)&Ms[d][quarter * 16 + e4 * 4];
            acc[e4 * 4 + 0] = fmaf(qv, m.x, acc[e4 * 4 + 0]);
            acc[e4 * 4 + 1] = fmaf(qv, m.y, acc[e4 * 4 + 1]);
            acc[e4 * 4 + 2] = fmaf(qv, m.z, acc[e4 * 4 + 2]);
            acc[e4 * 4 + 3] = fmaf(qv, m.w, acc[e4 * 4 + 3]);
        }
    }
    size_t obase = ((size_t)(b * 1024 + nt * 64 + r)) * CDIM + h * 64 + quarter * 16;
#pragma unroll
    for (int e2 = 0; e2 < 8; ++e2) {
        __half2 hh;
        hh.x = __float2half_rn(fmaxf(acc[e2 * 2 + 0], 0.f));
        hh.y = __float2half_rn(fmaxf(acc[e2 * 2 + 1], 0.f));
        *(__half2*)(g_attf + obase + e2 * 2) = hh;
    }
}

// ============================ host launch ============================
extern "C" void kernel_launch(void* const* d_in, const int* in_sizes, int n_in,
                              void* d_out, int out_size)
{
    (void)in_sizes; (void)n_in; (void)out_size;
    const float* x = (const float*)d_in[0];
    const float** p = (const float**)(d_in + 1);   // 24 params: 4 sets x 6

    cudaFuncSetAttribute(gemm_tc, cudaFuncAttributeMaxDynamicSharedMemorySize, GEMM_SMEM);

    prep_all<<<8224, 256>>>(x,
        p[0], p[1], p[2], p[3], p[4], p[5],
        p[6], p[7], p[8], p[9], p[10], p[11],
        p[12], p[13], p[14], p[15], p[16], p[17],
        p[18], p[19], p[20], p[21], p[22], p[23]);

    // fused QKV: grid (12, 64) = 768 CTAs, 256 thr, 2 CTAs/SM
    gemm_tc<<<dim3(12, 64), 256, GEMM_SMEM>>>(nullptr, 0);

    kv_outer_partial<<<dim3(64, 8), 128>>>();
    qm_relu_split<<<dim3(16, 8, 8), 256>>>();

    // P projection
    gemm_tc<<<dim3(4, 64), 256, GEMM_SMEM>>>((float*)d_out, 1);
}

// round 13
// speedup vs baseline: 2.3727x; 1.4560x over previous
#include <cuda_runtime.h>
#include <cuda_fp16.h>
#include <cstdint>

#define EPS_BN 1e-5f
#define SCALE_ATTN 0.125f
#define CDIM 512
#define MROWS 8192   // B*N

// ============================ scratch (static device mem) ============================
__device__ __align__(16) __half g_xf[MROWS*CDIM];
__device__ __align__(16) __half g_attf[MROWS*CDIM];
__device__ __align__(16) __half g_wq[CDIM*CDIM], g_wk[CDIM*CDIM];
__device__ __align__(16) __half g_wv[CDIM*CDIM], g_wp[CDIM*CDIM];
__device__ float g_bq[CDIM], g_bk[CDIM], g_bv[CDIM], g_bp[CDIM];
__device__ __align__(16) __half g_q[MROWS*CDIM], g_k[MROWS*CDIM], g_v[MROWS*CDIM];
__device__ __align__(16) float g_m[64*64*64];    // M^T per head: [bh][e][d], atomic-accumulated

// ============================ portable PTX helpers ============================
__device__ __forceinline__ uint32_t smem_u32(const void* p) {
    uint32_t a;
    asm("{ .reg .u64 t; cvta.to.shared.u64 t, %1; cvt.u32.u64 %0, t; }" : "=r"(a) : "l"(p));
    return a;
}
__device__ __forceinline__ void cp16(uint32_t saddr, const void* g) {
    asm volatile("cp.async.cg.shared.global [%0], [%1], 16;" :: "r"(saddr), "l"(g) : "memory");
}
__device__ __forceinline__ void cp_commit() {
    asm volatile("cp.async.commit_group;" ::: "memory");
}
template <int N> __device__ __forceinline__ void cp_wait() {
    asm volatile("cp.async.wait_group %0;" :: "n"(N) : "memory");
}
__device__ __forceinline__ void ldsm4(uint32_t* r, uint32_t addr) {
    asm volatile("ldmatrix.sync.aligned.m8n8.x4.shared.b16 {%0,%1,%2,%3}, [%4];"
                 : "=r"(r[0]), "=r"(r[1]), "=r"(r[2]), "=r"(r[3]) : "r"(addr));
}
__device__ __forceinline__ void mma_f16(float* c, const uint32_t* a, uint32_t b0, uint32_t b1) {
    asm volatile(
        "mma.sync.aligned.m16n8k16.row.col.f32.f16.f16.f32 "
        "{%0,%1,%2,%3}, {%4,%5,%6,%7}, {%8,%9}, {%0,%1,%2,%3};"
        : "+f"(c[0]), "+f"(c[1]), "+f"(c[2]), "+f"(c[3])
        : "r"(a[0]), "r"(a[1]), "r"(a[2]), "r"(a[3]), "r"(b0), "r"(b1));
}
// load 8 halves (16B) and convert to 8 floats
__device__ __forceinline__ void ld8h_to_f(const __half* g, float* out) {
    uint4 raw = *(const uint4*)g;
    const __half2* hp = (const __half2*)&raw;
#pragma unroll
    for (int i = 0; i < 4; ++i) {
        float2 f = __half22float2(hp[i]);
        out[i * 2 + 0] = f.x;
        out[i * 2 + 1] = f.y;
    }
}

// ============================ fused prep: BN-fold + x->fp16 + zero g_m ============================
__global__ void prep_all(
    const float* __restrict__ x,
    const float* __restrict__ w0, const float* __restrict__ b0, const float* __restrict__ g0,
    const float* __restrict__ be0, const float* __restrict__ mu0, const float* __restrict__ va0,
    const float* __restrict__ w1, const float* __restrict__ b1, const float* __restrict__ g1,
    const float* __restrict__ be1, const float* __restrict__ mu1, const float* __restrict__ va1,
    const float* __restrict__ w2, const float* __restrict__ b2, const float* __restrict__ g2,
    const float* __restrict__ be2, const float* __restrict__ mu2, const float* __restrict__ va2,
    const float* __restrict__ w3, const float* __restrict__ b3, const float* __restrict__ g3,
    const float* __restrict__ be3, const float* __restrict__ mu3, const float* __restrict__ va3)
{
    if (blockIdx.x < 4096) {
        int gi = blockIdx.x * 256 + threadIdx.x;   // 4 * 262144
        int s = gi >> 18;
        int i = gi & 262143;
        const float *w, *b, *g, *beta, *mu, *var;
        __half *wf;
        float* bias;
        if (s == 0) { w=w0;b=b0;g=g0;beta=be0;mu=mu0;var=va0; wf=g_wq;bias=g_bq; }
        else if (s == 1) { w=w1;b=b1;g=g1;beta=be1;mu=mu1;var=va1; wf=g_wk;bias=g_bk; }
        else if (s == 2) { w=w2;b=b2;g=g2;beta=be2;mu=mu2;var=va2; wf=g_wv;bias=g_bv; }
        else { w=w3;b=b3;g=g3;beta=be3;mu=mu3;var=va3; wf=g_wp;bias=g_bp; }
        int d = i >> 9;
        float sc = g[d] * rsqrtf(var[d] + EPS_BN);
        wf[i] = __float2half_rn(w[i] * sc);
        if ((i & 511) == 0) bias[d] = (b[d] - mu[d]) * sc + beta[d];
    } else if (blockIdx.x < 8192) {
        int i = (blockIdx.x - 4096) * 256 + threadIdx.x;   // over 1M float4
        float4 v = ((const float4*)x)[i];
        __half2 a; a.x = __float2half_rn(v.x); a.y = __float2half_rn(v.y);
        __half2 b; b.x = __float2half_rn(v.z); b.y = __float2half_rn(v.w);
        ((__half2*)g_xf)[i * 2 + 0] = a;
        ((__half2*)g_xf)[i * 2 + 1] = b;
    } else {
        int base = (blockIdx.x - 8192) * 256 + threadIdx.x;
        float4 z = {0.f, 0.f, 0.f, 0.f};
#pragma unroll
        for (int u = 0; u < 8; ++u)
            ((float4*)g_m)[base + u * 8192] = z;
    }
}

// ============================ HMMA GEMM (fp16, 1-product, BK=64) ============================
#define BK 64
#define NSTAGE (CDIM / BK)          // 8
#define RPITCH 144                  // 128B data + 16B pad
#define T_TB (128 * RPITCH)         // 18432 per operand tile
#define STAGEB (2 * T_TB)           // 36864: [Af, Wf]
#define GEMM_SMEM (2 * STAGEB)      // 73728

__global__ __launch_bounds__(256, 2)
void gemm_tc(float* __restrict__ Cext, int mode)
{
    extern __shared__ char smem[];
    const __half *Af, *Wf;
    const float* bias;
    __half* Ch = nullptr;
    float* Cf = nullptr;
    int bn;
    if (mode == 0) {
        int sel = blockIdx.x >> 2;          // 0=q, 1=k, 2=v
        bn = (blockIdx.x & 3) * 128;
        Af = g_xf;
        Wf = (sel == 0) ? g_wq : (sel == 1) ? g_wk : g_wv;
        bias = (sel == 0) ? g_bq : (sel == 1) ? g_bk : g_bv;
        Ch = (sel == 0) ? g_q : (sel == 1) ? g_k : g_v;
    } else {
        bn = blockIdx.x * 128;
        Af = g_attf;
        Wf = g_wp; bias = g_bp;
        Cf = Cext;
    }
    const int bm = blockIdx.y * 128;

    const uint32_t sb = smem_u32(smem);
    const int tid = threadIdx.x;
    const int wid = tid >> 5, lane = tid & 31;
    const int wm = wid & 1, wn = wid >> 1;   // 2(m) x 4(n), 64x32 per warp

    const __half* srcA = Af + (size_t)bm * CDIM;
    const __half* srcW = Wf + (size_t)bn * CDIM;

    auto load_stage = [&](int s, int buf) {
        uint32_t sbase = sb + buf * STAGEB;
        int kof = s * BK;
#pragma unroll
        for (int t = 0; t < 8; ++t) {
            int idx = tid + t * 256;
            int ten = idx >> 10;
            int v = idx & 1023;
            int row = v >> 3, ch = v & 7;
            const __half* g = (ten == 0 ? srcA : srcW) + (size_t)row * CDIM + kof + ch * 8;
            cp16(sbase + ten * T_TB + row * RPITCH + ch * 16, g);
        }
        cp_commit();
    };

    float acc[4][4][4];
#pragma unroll
    for (int i = 0; i < 4; ++i)
#pragma unroll
        for (int j = 0; j < 4; ++j)
#pragma unroll
            for (int k = 0; k < 4; ++k) acc[i][j][k] = 0.f;

    const int g8 = lane >> 3, l8 = lane & 7;
    const int a_row = (g8 & 1) * 8 + l8;
    const int a_k = (g8 >> 1) * 8;
    const int w_row = (g8 >> 1) * 8 + l8;
    const int w_k = (g8 & 1) * 8;

    const uint32_t aoffL = (wm * 64 + a_row) * RPITCH + a_k * 2;
    const uint32_t woffL = (wn * 32 + w_row) * RPITCH + w_k * 2;

    load_stage(0, 0);

    for (int s = 0; s < NSTAGE; ++s) {
        cp_wait<0>();
        __syncthreads();
        if (s + 1 < NSTAGE) load_stage(s + 1, (s + 1) & 1);

        const uint32_t base = sb + (s & 1) * STAGEB;
        const uint32_t aB = base + aoffL;
        const uint32_t wB = base + T_TB + woffL;

#pragma unroll
        for (int kk = 0; kk < BK; kk += 16) {
            uint32_t whf[2][4];
            ldsm4(whf[0], wB + kk * 2);
            ldsm4(whf[1], wB + 16 * RPITCH + kk * 2);
            uint32_t ahf[2][4];
            ldsm4(ahf[0], aB + kk * 2);
#pragma unroll
            for (int mi = 0; mi < 4; ++mi) {
                const int cur = mi & 1;
                if (mi < 3) ldsm4(ahf[cur ^ 1], aB + (mi + 1) * (16 * RPITCH) + kk * 2);
#pragma unroll
                for (int nj = 0; nj < 4; ++nj)
                    mma_f16(acc[mi][nj], ahf[cur], whf[nj >> 1][(nj & 1) * 2], whf[nj >> 1][(nj & 1) * 2 + 1]);
            }
        }
    }

    const int r_in = lane >> 2;
    const int c_in = (lane & 3) * 2;
#pragma unroll
    for (int mi = 0; mi < 4; ++mi) {
        int r0 = bm + wm * 64 + mi * 16 + r_in;
#pragma unroll
        for (int nj = 0; nj < 4; ++nj) {
            int c0 = bn + wn * 32 + nj * 8 + c_in;
            float b0 = bias[c0], b1 = bias[c0 + 1];
            float v00 = fmaxf(acc[mi][nj][0] + b0, 0.f);
            float v01 = fmaxf(acc[mi][nj][1] + b1, 0.f);
            float v10 = fmaxf(acc[mi][nj][2] + b0, 0.f);
            float v11 = fmaxf(acc[mi][nj][3] + b1, 0.f);
            if (mode == 0) {
                __half2 lo; lo.x = __float2half_rn(v00); lo.y = __float2half_rn(v01);
                __half2 hi; hi.x = __float2half_rn(v10); hi.y = __float2half_rn(v11);
                *(__half2*)(Ch + (size_t)r0 * CDIM + c0) = lo;
                *(__half2*)(Ch + (size_t)(r0 + 8) * CDIM + c0) = hi;
            } else {
                float2 lo = {v00, v01};
                float2 hi = {v10, v11};
                *(float2*)(Cf + (size_t)r0 * CDIM + c0) = lo;
                *(float2*)(Cf + (size_t)(r0 + 8) * CDIM + c0) = hi;
            }
        }
    }
}

// ============================ kv_outer: M^T[e][d] += sum k[n][d] v[n][e] ============================
__global__ __launch_bounds__(128)
void kv_outer_partial()
{
    int bh = blockIdx.x, part = blockIdx.y;
    int b = bh >> 3, h = bh & 7;
    __shared__ float Ks[32][64];
    __shared__ float Vs[32][64];
    int tid = threadIdx.x;
    int tx = tid & 15;                // e-group: 4 per thread
    int ty = tid >> 4;                // d-group: 8 per thread
    const __half* kbase = g_k + ((size_t)b * 1024) * CDIM + h * 64;
    const __half* vbase = g_v + ((size_t)b * 1024) * CDIM + h * 64;

    float acc[8][4];
#pragma unroll
    for (int i = 0; i < 8; ++i)
#pragma unroll
        for (int j = 0; j < 4; ++j) acc[i][j] = 0.f;

    int nbeg = part * 128;
    for (int n0 = nbeg; n0 < nbeg + 128; n0 += 32) {
#pragma unroll
        for (int u = 0; u < 2; ++u) {
            int v = tid + u * 128;
            int r = v >> 3, c8 = v & 7;
            ld8h_to_f(kbase + (size_t)(n0 + r) * CDIM + c8 * 8, &Ks[r][c8 * 8]);
            ld8h_to_f(vbase + (size_t)(n0 + r) * CDIM + c8 * 8, &Vs[r][c8 * 8]);
        }
        __syncthreads();
#pragma unroll
        for (int nn = 0; nn < 32; ++nn) {
            float4 k0 = *(const float4*)&Ks[nn][ty * 8];
            float4 k1 = *(const float4*)&Ks[nn][ty * 8 + 4];
            float4 vv = *(const float4*)&Vs[nn][tx * 4];
            float ka[8] = {k0.x, k0.y, k0.z, k0.w, k1.x, k1.y, k1.z, k1.w};
            float va[4] = {vv.x, vv.y, vv.z, vv.w};
#pragma unroll
            for (int i = 0; i < 8; ++i)
#pragma unroll
                for (int j = 0; j < 4; ++j)
                    acc[i][j] = fmaf(ka[i], va[j], acc[i][j]);
        }
        __syncthreads();
    }

    // transposed accumulate: g_m[bh][e][d]
    float* mdst = g_m + (size_t)bh * 4096;
#pragma unroll
    for (int i = 0; i < 8; ++i) {
        int d = ty * 8 + i;
#pragma unroll
        for (int j = 0; j < 4; ++j) {
            int e = tx * 4 + j;
            atomicAdd(mdst + e * 64 + d, acc[i][j]);
        }
    }
}

// ============================ qm via tensor cores: att = relu(q @ M) -> fp16 ============================
// Per CTA: one (b, h, 128-row tile). A = q[128,64] fp16 (smem, pitch 144),
// B = M^T[e][d] fp16 (converted from g_m with SCALE, pitch 144). 4 warps x (32m x 64n).
#define QM_QPITCH 144
#define QM_Q_TB (128 * QM_QPITCH)   // 18432

__global__ __launch_bounds__(128)
void qm_tc()
{
    __shared__ __align__(16) char qs[QM_Q_TB];
    __shared__ __align__(16) char ms[64 * QM_QPITCH];   // 9216

    int nt = blockIdx.x;   // 0..7 (128-row tiles)
    int h = blockIdx.y, b = blockIdx.z;
    int bh = b * 8 + h;
    int tid = threadIdx.x;
    int wid = tid >> 5, lane = tid & 31;

    const uint32_t qB0 = smem_u32(qs);
    const uint32_t mB0 = smem_u32(ms);

    const __half* qbase = g_q + ((size_t)(b * 1024 + nt * 128)) * CDIM + h * 64;
    // q tile: 128 rows x 8 chunks of 16B = 1024 chunks; 8 per thread
#pragma unroll
    for (int t = 0; t < 8; ++t) {
        int idx = tid + t * 128;
        int row = idx >> 3, ch = idx & 7;
        cp16(qB0 + row * QM_QPITCH + ch * 16, qbase + (size_t)row * CDIM + ch * 8);
    }
    cp_commit();

    // M^T: 4096 floats -> fp16 (x SCALE); 2048 half2 writes, 16 per thread
    const float* mbase = g_m + (size_t)bh * 4096;
#pragma unroll
    for (int u = 0; u < 16; ++u) {
        int idx = tid + u * 128;        // 0..2047
        int e = idx >> 5, d2 = idx & 31;
        float2 v = *(const float2*)(mbase + e * 64 + d2 * 2);
        __half2 hv;
        hv.x = __float2half_rn(v.x * SCALE_ATTN);
        hv.y = __float2half_rn(v.y * SCALE_ATTN);
        *(__half2*)(ms + e * QM_QPITCH + d2 * 4) = hv;
    }
    cp_wait<0>();
    __syncthreads();

    const int g8 = lane >> 3, l8 = lane & 7;
    const int a_row = (g8 & 1) * 8 + l8;
    const int a_k = (g8 >> 1) * 8;
    const int w_row = (g8 >> 1) * 8 + l8;
    const int w_k = (g8 & 1) * 8;

    const uint32_t aB = qB0 + (wid * 32 + a_row) * QM_QPITCH + a_k * 2;
    const uint32_t wB = mB0 + w_row * QM_QPITCH + w_k * 2;

    float acc[2][8][4];
#pragma unroll
    for (int i = 0; i < 2; ++i)
#pragma unroll
        for (int j = 0; j < 8; ++j)
#pragma unroll
            for (int k = 0; k < 4; ++k) acc[i][j][k] = 0.f;

#pragma unroll
    for (int kk = 0; kk < 64; kk += 16) {
        uint32_t bf[4][4];
#pragma unroll
        for (int j = 0; j < 4; ++j)
            ldsm4(bf[j], wB + j * (16 * QM_QPITCH) + kk * 2);
        uint32_t af[2][4];
        ldsm4(af[0], aB + kk * 2);
        ldsm4(af[1], aB + 16 * QM_QPITCH + kk * 2);
#pragma unroll
        for (int mi = 0; mi < 2; ++mi)
#pragma unroll
            for (int nj = 0; nj < 8; ++nj)
                mma_f16(acc[mi][nj], af[mi], bf[nj >> 1][(nj & 1) * 2], bf[nj >> 1][(nj & 1) * 2 + 1]);
    }

    const int r_in = lane >> 2;
    const int c_in = (lane & 3) * 2;
#pragma unroll
    for (int mi = 0; mi < 2; ++mi) {
        size_t r0 = (size_t)(b * 1024 + nt * 128 + wid * 32 + mi * 16 + r_in);
#pragma unroll
        for (int nj = 0; nj < 8; ++nj) {
            int c0 = h * 64 + nj * 8 + c_in;
            __half2 lo, hi;
            lo.x = __float2half_rn(fmaxf(acc[mi][nj][0], 0.f));
            lo.y = __float2half_rn(fmaxf(acc[mi][nj][1], 0.f));
            hi.x = __float2half_rn(fmaxf(acc[mi][nj][2], 0.f));
            hi.y = __float2half_rn(fmaxf(acc[mi][nj][3], 0.f));
            *(__half2*)(g_attf + r0 * CDIM + c0) = lo;
            *(__half2*)(g_attf + (r0 + 8) * CDIM + c0) = hi;
        }
    }
}

// ============================ host launch ============================
extern "C" void kernel_launch(void* const* d_in, const int* in_sizes, int n_in,
                              void* d_out, int out_size)
{
    (void)in_sizes; (void)n_in; (void)out_size;
    const float* x = (const float*)d_in[0];
    const float** p = (const float**)(d_in + 1);   // 24 params: 4 sets x 6

    cudaFuncSetAttribute(gemm_tc, cudaFuncAttributeMaxDynamicSharedMemorySize, GEMM_SMEM);

    prep_all<<<8224, 256>>>(x,
        p[0], p[1], p[2], p[3], p[4], p[5],
        p[6], p[7], p[8], p[9], p[10], p[11],
        p[12], p[13], p[14], p[15], p[16], p[17],
        p[18], p[19], p[20], p[21], p[22], p[23]);

    // fused QKV: grid (12, 64) = 768 CTAs
    gemm_tc<<<dim3(12, 64), 256, GEMM_SMEM>>>(nullptr, 0);

    kv_outer_partial<<<dim3(64, 8), 128>>>();
    qm_tc<<<dim3(8, 8, 8), 128>>>();

    // P projection
    gemm_tc<<<dim3(4, 64), 256, GEMM_SMEM>>>((float*)d_out, 1);
}

// round 15
// speedup vs baseline: 2.8860x; 1.2163x over previous
#include <cuda_runtime.h>
#include <cuda_fp16.h>
#include <cstdint>

#define EPS_BN 1e-5f
#define SCALE_ATTN 0.125f
#define CDIM 512
#define MROWS 8192   // B*N

// ============================ scratch (static device mem) ============================
__device__ __align__(16) __half g_xf[MROWS*CDIM];
__device__ __align__(16) __half g_attf[MROWS*CDIM];
__device__ __align__(16) __half g_wq[CDIM*CDIM], g_wk[CDIM*CDIM];
__device__ __align__(16) __half g_wv[CDIM*CDIM], g_wp[CDIM*CDIM];
__device__ float g_bq[CDIM], g_bk[CDIM], g_bv[CDIM], g_bp[CDIM];
__device__ __align__(16) __half g_q[MROWS*CDIM];                 // [row][C] normal
__device__ __align__(16) __half g_kT[MROWS*CDIM], g_vT[MROWS*CDIM]; // [bh][d][n=1024] transposed
__device__ __align__(16) float g_m[64*64*64];    // M^T per head: [bh][e][d]

// ============================ portable PTX helpers ============================
__device__ __forceinline__ uint32_t smem_u32(const void* p) {
    uint32_t a;
    asm("{ .reg .u64 t; cvta.to.shared.u64 t, %1; cvt.u32.u64 %0, t; }" : "=r"(a) : "l"(p));
    return a;
}
__device__ __forceinline__ void cp16(uint32_t saddr, const void* g) {
    asm volatile("cp.async.cg.shared.global [%0], [%1], 16;" :: "r"(saddr), "l"(g) : "memory");
}
__device__ __forceinline__ void cp_commit() {
    asm volatile("cp.async.commit_group;" ::: "memory");
}
template <int N> __device__ __forceinline__ void cp_wait() {
    asm volatile("cp.async.wait_group %0;" :: "n"(N) : "memory");
}
__device__ __forceinline__ void ldsm4(uint32_t* r, uint32_t addr) {
    asm volatile("ldmatrix.sync.aligned.m8n8.x4.shared.b16 {%0,%1,%2,%3}, [%4];"
                 : "=r"(r[0]), "=r"(r[1]), "=r"(r[2]), "=r"(r[3]) : "r"(addr));
}
__device__ __forceinline__ void mma_f16(float* c, const uint32_t* a, uint32_t b0, uint32_t b1) {
    asm volatile(
        "mma.sync.aligned.m16n8k16.row.col.f32.f16.f16.f32 "
        "{%0,%1,%2,%3}, {%4,%5,%6,%7}, {%8,%9}, {%0,%1,%2,%3};"
        : "+f"(c[0]), "+f"(c[1]), "+f"(c[2]), "+f"(c[3])
        : "r"(a[0]), "r"(a[1]), "r"(a[2]), "r"(a[3]), "r"(b0), "r"(b1));
}

// ============================ prep: BN-fold (ILP4) + x->fp16 (ILP4) ============================
__global__ void prep_all(
    const float* __restrict__ x,
    const float* __restrict__ w0, const float* __restrict__ b0, const float* __restrict__ g0,
    const float* __restrict__ be0, const float* __restrict__ mu0, const float* __restrict__ va0,
    const float* __restrict__ w1, const float* __restrict__ b1, const float* __restrict__ g1,
    const float* __restrict__ be1, const float* __restrict__ mu1, const float* __restrict__ va1,
    const float* __restrict__ w2, const float* __restrict__ b2, const float* __restrict__ g2,
    const float* __restrict__ be2, const float* __restrict__ mu2, const float* __restrict__ va2,
    const float* __restrict__ w3, const float* __restrict__ b3, const float* __restrict__ g3,
    const float* __restrict__ be3, const float* __restrict__ mu3, const float* __restrict__ va3)
{
    int tid = threadIdx.x;
    if (blockIdx.x < 256) {
        int base = blockIdx.x * 256 + tid;      // [0, 65536)
#pragma unroll
        for (int u = 0; u < 4; ++u) {
            int idx = base + u * 65536;          // float4 index over 262144
            int s = idx >> 16;
            int i4 = idx & 65535;
            const float *w, *b, *g, *beta, *mu, *var;
            __half* wf; float* bias;
            if (s == 0) { w=w0;b=b0;g=g0;beta=be0;mu=mu0;var=va0; wf=g_wq;bias=g_bq; }
            else if (s == 1) { w=w1;b=b1;g=g1;beta=be1;mu=mu1;var=va1; wf=g_wk;bias=g_bk; }
            else if (s == 2) { w=w2;b=b2;g=g2;beta=be2;mu=mu2;var=va2; wf=g_wv;bias=g_bv; }
            else { w=w3;b=b3;g=g3;beta=be3;mu=mu3;var=va3; wf=g_wp;bias=g_bp; }
            int i = i4 * 4;
            int d = i >> 9;
            float sc = g[d] * rsqrtf(var[d] + EPS_BN);
            float4 wv = ((const float4*)w)[i4];
            __half2 h0, h1;
            h0.x = __float2half_rn(wv.x * sc); h0.y = __float2half_rn(wv.y * sc);
            h1.x = __float2half_rn(wv.z * sc); h1.y = __float2half_rn(wv.w * sc);
            ((__half2*)wf)[i4 * 2 + 0] = h0;
            ((__half2*)wf)[i4 * 2 + 1] = h1;
            if ((i & 511) == 0) bias[d] = (b[d] - mu[d]) * sc + beta[d];
        }
    } else {
        int base = (blockIdx.x - 256) * 256 + tid;   // [0, 262144)
#pragma unroll
        for (int u = 0; u < 4; ++u) {
            int i = base + u * 262144;               // float4 index over 1M
            float4 v = ((const float4*)x)[i];
            __half2 a; a.x = __float2half_rn(v.x); a.y = __float2half_rn(v.y);
            __half2 b; b.x = __float2half_rn(v.z); b.y = __float2half_rn(v.w);
            ((__half2*)g_xf)[i * 2 + 0] = a;
            ((__half2*)g_xf)[i * 2 + 1] = b;
        }
    }
}

// ============================ HMMA GEMM (fp16, 1-product, BK=64) ============================
// mode 0: fused QKV from xf. sel 0 -> g_q normal [row][C]; sel 1/2 -> g_kT/g_vT transposed.
// mode 1: P from attf -> fp32 d_out.
#define BK 64
#define NSTAGE (CDIM / BK)          // 8
#define RPITCH 144                  // 128B data + 16B pad
#define T_TB (128 * RPITCH)         // 18432 per operand tile
#define STAGEB (2 * T_TB)           // 36864: [Af, Wf]
#define GEMM_SMEM (2 * STAGEB)      // 73728

__global__ __launch_bounds__(256, 2)
void gemm_tc(float* __restrict__ Cext, int mode)
{
    extern __shared__ char smem[];
    const __half *Af, *Wf;
    const float* bias;
    int sel = 0, bn;
    if (mode == 0) {
        sel = blockIdx.x >> 2;              // 0=q, 1=k, 2=v
        bn = (blockIdx.x & 3) * 128;
        Af = g_xf;
        Wf = (sel == 0) ? g_wq : (sel == 1) ? g_wk : g_wv;
        bias = (sel == 0) ? g_bq : (sel == 1) ? g_bk : g_bv;
    } else {
        bn = blockIdx.x * 128;
        Af = g_attf;
        Wf = g_wp; bias = g_bp;
    }
    const int bm = blockIdx.y * 128;

    const uint32_t sb = smem_u32(smem);
    const int tid = threadIdx.x;
    const int wid = tid >> 5, lane = tid & 31;
    const int wm = wid & 1, wn = wid >> 1;   // 2(m) x 4(n), 64x32 per warp

    const __half* srcA = Af + (size_t)bm * CDIM;
    const __half* srcW = Wf + (size_t)bn * CDIM;

    auto load_stage = [&](int s, int buf) {
        uint32_t sbase = sb + buf * STAGEB;
        int kof = s * BK;
#pragma unroll
        for (int t = 0; t < 8; ++t) {
            int idx = tid + t * 256;
            int ten = idx >> 10;
            int v = idx & 1023;
            int row = v >> 3, ch = v & 7;
            const __half* g = (ten == 0 ? srcA : srcW) + (size_t)row * CDIM + kof + ch * 8;
            cp16(sbase + ten * T_TB + row * RPITCH + ch * 16, g);
        }
        cp_commit();
    };

    float acc[4][4][4];
#pragma unroll
    for (int i = 0; i < 4; ++i)
#pragma unroll
        for (int j = 0; j < 4; ++j)
#pragma unroll
            for (int k = 0; k < 4; ++k) acc[i][j][k] = 0.f;

    const int g8 = lane >> 3, l8 = lane & 7;
    const int a_row = (g8 & 1) * 8 + l8;
    const int a_k = (g8 >> 1) * 8;
    const int w_row = (g8 >> 1) * 8 + l8;
    const int w_k = (g8 & 1) * 8;

    const uint32_t aoffL = (wm * 64 + a_row) * RPITCH + a_k * 2;
    const uint32_t woffL = (wn * 32 + w_row) * RPITCH + w_k * 2;

    load_stage(0, 0);

    for (int s = 0; s < NSTAGE; ++s) {
        cp_wait<0>();
        __syncthreads();
        if (s + 1 < NSTAGE) load_stage(s + 1, (s + 1) & 1);

        const uint32_t base = sb + (s & 1) * STAGEB;
        const uint32_t aB = base + aoffL;
        const uint32_t wB = base + T_TB + woffL;

#pragma unroll
        for (int kk = 0; kk < BK; kk += 16) {
            uint32_t whf[2][4];
            ldsm4(whf[0], wB + kk * 2);
            ldsm4(whf[1], wB + 16 * RPITCH + kk * 2);
            uint32_t ahf[2][4];
            ldsm4(ahf[0], aB + kk * 2);
#pragma unroll
            for (int mi = 0; mi < 4; ++mi) {
                const int cur = mi & 1;
                if (mi < 3) ldsm4(ahf[cur ^ 1], aB + (mi + 1) * (16 * RPITCH) + kk * 2);
#pragma unroll
                for (int nj = 0; nj < 4; ++nj)
                    mma_f16(acc[mi][nj], ahf[cur], whf[nj >> 1][(nj & 1) * 2], whf[nj >> 1][(nj & 1) * 2 + 1]);
            }
        }
    }

    const int r_in = lane >> 2;
    const int c_in = (lane & 3) * 2;
#pragma unroll
    for (int mi = 0; mi < 4; ++mi) {
        int r0 = bm + wm * 64 + mi * 16 + r_in;
#pragma unroll
        for (int nj = 0; nj < 4; ++nj) {
            int c0 = bn + wn * 32 + nj * 8 + c_in;
            float b0 = bias[c0], b1 = bias[c0 + 1];
            float v00 = fmaxf(acc[mi][nj][0] + b0, 0.f);
            float v01 = fmaxf(acc[mi][nj][1] + b1, 0.f);
            float v10 = fmaxf(acc[mi][nj][2] + b0, 0.f);
            float v11 = fmaxf(acc[mi][nj][3] + b1, 0.f);
            if (mode == 1) {
                float2 lo = {v00, v01};
                float2 hi = {v10, v11};
                *(float2*)(Cext + (size_t)r0 * CDIM + c0) = lo;
                *(float2*)(Cext + (size_t)(r0 + 8) * CDIM + c0) = hi;
            } else if (sel == 0) {
                __half2 lo; lo.x = __float2half_rn(v00); lo.y = __float2half_rn(v01);
                __half2 hi; hi.x = __float2half_rn(v10); hi.y = __float2half_rn(v11);
                *(__half2*)(g_q + (size_t)r0 * CDIM + c0) = lo;
                *(__half2*)(g_q + (size_t)(r0 + 8) * CDIM + c0) = hi;
            } else {
                __half* T = (sel == 1) ? g_kT : g_vT;
                int b_ = r0 >> 10, n_ = r0 & 1023;
                int hh = c0 >> 6, dd = c0 & 63;
                size_t rowb = ((size_t)(b_ * 8 + hh) * 64 + dd) * 1024;
                T[rowb + n_] = __float2half_rn(v00);
                T[rowb + 1024 + n_] = __float2half_rn(v01);
                T[rowb + n_ + 8] = __float2half_rn(v10);
                T[rowb + 1024 + n_ + 8] = __float2half_rn(v11);
            }
        }
    }
}

// ============================ kv via tensor cores: M^T[e][d] = sum_n vT[e][n] kT[d][n] ============================
// One CTA per bh, 4 warps (each m16 e-tile x full d64), K = 1024 over 8 chunks of 128, double-buffered.
#define KV_PITCH 272                 // 128 fp16 = 256B + 16 pad
#define KV_TB (64 * KV_PITCH)        // 17408 per tensor per chunk
#define KV_STG (2 * KV_TB)           // 34816: [vT, kT]
#define KV_SMEM (2 * KV_STG)         // 69632

__global__ __launch_bounds__(128)
void kv_tc()
{
    extern __shared__ char smem[];
    int bh = blockIdx.x;
    int tid = threadIdx.x;
    int wid = tid >> 5, lane = tid & 31;

    const uint32_t sb = smem_u32(smem);
    const __half* vsrc = g_vT + (size_t)bh * 64 * 1024;
    const __half* ksrc = g_kT + (size_t)bh * 64 * 1024;

    // chunk load: 64 rows x 16 cp16 per tensor = 2048 cp16 total, 16/thread
    auto load_chunk = [&](int c, int buf) {
        uint32_t sbase = sb + buf * KV_STG;
        int n0 = c * 128;
#pragma unroll
        for (int t = 0; t < 16; ++t) {
            int idx = tid + t * 128;
            int ten = idx >> 10;              // 0=vT 1=kT
            int v = idx & 1023;
            int row = v >> 4, ch = v & 15;
            const __half* g = (ten == 0 ? vsrc : ksrc) + (size_t)row * 1024 + n0 + ch * 8;
            cp16(sbase + ten * KV_TB + row * KV_PITCH + ch * 16, g);
        }
        cp_commit();
    };

    float acc[8][4];
#pragma unroll
    for (int j = 0; j < 8; ++j)
#pragma unroll
        for (int k = 0; k < 4; ++k) acc[j][k] = 0.f;

    const int g8 = lane >> 3, l8 = lane & 7;
    const int a_row = (g8 & 1) * 8 + l8;
    const int a_k = (g8 >> 1) * 8;
    const int w_row = (g8 >> 1) * 8 + l8;
    const int w_k = (g8 & 1) * 8;

    const uint32_t aoffL = (wid * 16 + a_row) * KV_PITCH + a_k * 2;   // A = vT, warp e-tile
    const uint32_t woffL = w_row * KV_PITCH + w_k * 2;                // B = kT

    load_chunk(0, 0);

    for (int c = 0; c < 8; ++c) {
        cp_wait<0>();
        __syncthreads();
        if (c + 1 < 8) load_chunk(c + 1, (c + 1) & 1);

        const uint32_t base = sb + (c & 1) * KV_STG;
        const uint32_t aB = base + aoffL;
        const uint32_t wB = base + KV_TB + woffL;

#pragma unroll
        for (int kk = 0; kk < 128; kk += 16) {
            uint32_t bf[4][4];
#pragma unroll
            for (int j = 0; j < 4; ++j)
                ldsm4(bf[j], wB + j * (16 * KV_PITCH) + kk * 2);
            uint32_t af[4];
            ldsm4(af, aB + kk * 2);
#pragma unroll
            for (int nj = 0; nj < 8; ++nj)
                mma_f16(acc[nj], af, bf[nj >> 1][(nj & 1) * 2], bf[nj >> 1][(nj & 1) * 2 + 1]);
        }
    }

    const int r_in = lane >> 2;
    const int c_in = (lane & 3) * 2;
    float* mdst = g_m + (size_t)bh * 4096;
#pragma unroll
    for (int nj = 0; nj < 8; ++nj) {
        int e0 = wid * 16 + r_in;
        int d0 = nj * 8 + c_in;
        float2 lo = {acc[nj][0], acc[nj][1]};
        float2 hi = {acc[nj][2], acc[nj][3]};
        *(float2*)(mdst + e0 * 64 + d0) = lo;
        *(float2*)(mdst + (e0 + 8) * 64 + d0) = hi;
    }
}

// ============================ qm via tensor cores: att = relu(q @ M) -> fp16 ============================
#define QM_QPITCH 144
#define QM_Q_TB (128 * QM_QPITCH)   // 18432

__global__ __launch_bounds__(128)
void qm_tc()
{
    __shared__ __align__(16) char qs[QM_Q_TB];
    __shared__ __align__(16) char ms[64 * QM_QPITCH];

    int nt = blockIdx.x;   // 0..7 (128-row tiles)
    int h = blockIdx.y, b = blockIdx.z;
    int bh = b * 8 + h;
    int tid = threadIdx.x;
    int wid = tid >> 5, lane = tid & 31;

    const uint32_t qB0 = smem_u32(qs);
    const uint32_t mB0 = smem_u32(ms);

    const __half* qbase = g_q + ((size_t)(b * 1024 + nt * 128)) * CDIM + h * 64;
#pragma unroll
    for (int t = 0; t < 8; ++t) {
        int idx = tid + t * 128;
        int row = idx >> 3, ch = idx & 7;
        cp16(qB0 + row * QM_QPITCH + ch * 16, qbase + (size_t)row * CDIM + ch * 8);
    }
    cp_commit();

    const float* mbase = g_m + (size_t)bh * 4096;
#pragma unroll
    for (int u = 0; u < 16; ++u) {
        int idx = tid + u * 128;
        int e = idx >> 5, d2 = idx & 31;
        float2 v = *(const float2*)(mbase + e * 64 + d2 * 2);
        __half2 hv;
        hv.x = __float2half_rn(v.x * SCALE_ATTN);
        hv.y = __float2half_rn(v.y * SCALE_ATTN);
        *(__half2*)(ms + e * QM_QPITCH + d2 * 4) = hv;
    }
    cp_wait<0>();
    __syncthreads();

    const int g8 = lane >> 3, l8 = lane & 7;
    const int a_row = (g8 & 1) * 8 + l8;
    const int a_k = (g8 >> 1) * 8;
    const int w_row = (g8 >> 1) * 8 + l8;
    const int w_k = (g8 & 1) * 8;

    const uint32_t aB = qB0 + (wid * 32 + a_row) * QM_QPITCH + a_k * 2;
    const uint32_t wB = mB0 + w_row * QM_QPITCH + w_k * 2;

    float acc[2][8][4];
#pragma unroll
    for (int i = 0; i < 2; ++i)
#pragma unroll
        for (int j = 0; j < 8; ++j)
#pragma unroll
            for (int k = 0; k < 4; ++k) acc[i][j][k] = 0.f;

#pragma unroll
    for (int kk = 0; kk < 64; kk += 16) {
        uint32_t bf[4][4];
#pragma unroll
        for (int j = 0; j < 4; ++j)
            ldsm4(bf[j], wB + j * (16 * QM_QPITCH) + kk * 2);
        uint32_t af[2][4];
        ldsm4(af[0], aB + kk * 2);
        ldsm4(af[1], aB + 16 * QM_QPITCH + kk * 2);
#pragma unroll
        for (int mi = 0; mi < 2; ++mi)
#pragma unroll
            for (int nj = 0; nj < 8; ++nj)
                mma_f16(acc[mi][nj], af[mi], bf[nj >> 1][(nj & 1) * 2], bf[nj >> 1][(nj & 1) * 2 + 1]);
    }

    const int r_in = lane >> 2;
    const int c_in = (lane & 3) * 2;
#pragma unroll
    for (int mi = 0; mi < 2; ++mi) {
        size_t r0 = (size_t)(b * 1024 + nt * 128 + wid * 32 + mi * 16 + r_in);
#pragma unroll
        for (int nj = 0; nj < 8; ++nj) {
            int c0 = h * 64 + nj * 8 + c_in;
            __half2 lo, hi;
            lo.x = __float2half_rn(fmaxf(acc[mi][nj][0], 0.f));
            lo.y = __float2half_rn(fmaxf(acc[mi][nj][1], 0.f));
            hi.x = __float2half_rn(fmaxf(acc[mi][nj][2], 0.f));
            hi.y = __float2half_rn(fmaxf(acc[mi][nj][3], 0.f));
            *(__half2*)(g_attf + r0 * CDIM + c0) = lo;
            *(__half2*)(g_attf + (r0 + 8) * CDIM + c0) = hi;
        }
    }
}

// ============================ host launch ============================
extern "C" void kernel_launch(void* const* d_in, const int* in_sizes, int n_in,
                              void* d_out, int out_size)
{
    (void)in_sizes; (void)n_in; (void)out_size;
    const float* x = (const float*)d_in[0];
    const float** p = (const float**)(d_in + 1);   // 24 params: 4 sets x 6

    cudaFuncSetAttribute(gemm_tc, cudaFuncAttributeMaxDynamicSharedMemorySize, GEMM_SMEM);
    cudaFuncSetAttribute(kv_tc, cudaFuncAttributeMaxDynamicSharedMemorySize, KV_SMEM);

    prep_all<<<1280, 256>>>(x,
        p[0], p[1], p[2], p[3], p[4], p[5],
        p[6], p[7], p[8], p[9], p[10], p[11],
        p[12], p[13], p[14], p[15], p[16], p[17],
        p[18], p[19], p[20], p[21], p[22], p[23]);

    // fused QKV: grid (12, 64) = 768 CTAs
    gemm_tc<<<dim3(12, 64), 256, GEMM_SMEM>>>(nullptr, 0);

    kv_tc<<<64, 128, KV_SMEM>>>();
    qm_tc<<<dim3(8, 8, 8), 128>>>();

    // P projection
    gemm_tc<<<dim3(4, 64), 256, GEMM_SMEM>>>((float*)d_out, 1);
}